// round 1
// baseline (speedup 1.0000x reference)
#include <cuda_runtime.h>
#include <math.h>

#define BB 1024
#define TT 70
#define HH 150
#define DIN 300      // per-layer input width (E = 2H = 300)
#define G4 600       // 4*H
#define BT (BB*TT)   // 71680
#define DEPTH 5

// ---------------- scratch (static device globals; no allocation) ------------
__device__ float g_xz[2][BT][G4];     // precomputed x@Wx+b, per direction (344 MB)
__device__ float g_buf[2][BT][DIN];   // ping-pong layer activations (172 MB)
__device__ float g_h[2][BB][HH];
__device__ float g_c[2][BB][HH];
__device__ int   g_lens[BB];

// ---------------- small kernels ---------------------------------------------
__global__ void lens_kernel(const int* __restrict__ mask) {
    int b = blockIdx.x * blockDim.x + threadIdx.x;
    if (b < BB) {
        int s = 0;
        #pragma unroll
        for (int t = 0; t < TT; t++) s += mask[b * TT + t];
        g_lens[b] = s;
    }
}

__global__ void zero_states() {
    int i = blockIdx.x * blockDim.x + threadIdx.x;
    if (i < 2 * BB * HH) {
        ((float*)g_h)[i] = 0.f;
        ((float*)g_c)[i] = 0.f;
    }
}

// ---------------- input projection: g_xz[dir] = A @ Wx + bias ---------------
// A: [BT, 300] row-major. Wx: rows [0,300) of kernel [450,600]. C: [BT,600].
// Tiles: BM=128, BN=64, BK=20 (300 = 15*20 exact). 256 threads, 8x4 per thread.
__global__ void __launch_bounds__(256) xz_gemm(
    const float* __restrict__ A,
    const float* __restrict__ Wf, const float* __restrict__ bf,
    const float* __restrict__ Wb, const float* __restrict__ bb)
{
    const int dir = blockIdx.z;
    const float* __restrict__ Wg   = dir ? Wb : Wf;
    const float* __restrict__ bias = dir ? bb : bf;
    const int n0 = blockIdx.x * 64;
    const int m0 = blockIdx.y * 128;

    __shared__ float As[20][128];
    __shared__ float Ws[20][64];

    const int tid = threadIdx.x;
    const int tm = (tid >> 4) * 8;   // 0..120 step 8
    const int tn = (tid & 15) * 4;   // 0..60 step 4

    float acc[8][4];
    #pragma unroll
    for (int r = 0; r < 8; r++)
        #pragma unroll
        for (int c = 0; c < 4; c++) acc[r][c] = 0.f;

    for (int kt = 0; kt < DIN; kt += 20) {
        #pragma unroll
        for (int i = 0; i < 10; i++) {                 // 128*20 = 2560 elems
            int idx = tid + i * 256;
            int m = idx / 20, k = idx % 20;
            As[k][m] = A[(size_t)(m0 + m) * DIN + kt + k];
        }
        #pragma unroll
        for (int i = 0; i < 5; i++) {                  // 20*64 = 1280 elems
            int idx = tid + i * 256;
            int k = idx >> 6, n = idx & 63;
            int col = n0 + n;
            Ws[k][n] = (col < G4) ? Wg[(size_t)(kt + k) * G4 + col] : 0.f;
        }
        __syncthreads();
        #pragma unroll
        for (int k = 0; k < 20; k++) {
            float a[8], w[4];
            #pragma unroll
            for (int r = 0; r < 8; r++) a[r] = As[k][tm + r];
            #pragma unroll
            for (int c = 0; c < 4; c++) w[c] = Ws[k][tn + c];
            #pragma unroll
            for (int r = 0; r < 8; r++)
                #pragma unroll
                for (int c = 0; c < 4; c++)
                    acc[r][c] = fmaf(a[r], w[c], acc[r][c]);
        }
        __syncthreads();
    }

    float* __restrict__ Cout = &g_xz[dir][0][0];
    #pragma unroll
    for (int c = 0; c < 4; c++) {
        int col = n0 + tn + c;
        if (col < G4) {
            float bv = bias[col];
            #pragma unroll
            for (int r = 0; r < 8; r++)
                Cout[(size_t)(m0 + tm + r) * G4 + col] = acc[r][c] + bv;
        }
    }
}

// ---------------- fused recurrent step --------------------------------------
// Per step: z = g_xz[dir][b, t] + h @ Wh ; gate math ; update h,c ; write out.
// Block = 64 batch rows x 32 hidx x 4 gates. grid = (5, 16, 2dirs).
__device__ __forceinline__ float sigmf(float x) { return 1.f / (1.f + expf(-x)); }

__global__ void __launch_bounds__(256) lstm_step(
    int step,
    const float* __restrict__ Whf,   // [150,600], rows 300.. of fw kernel
    const float* __restrict__ Whb,
    float* __restrict__ out)         // [BT, 300]
{
    const int dir = blockIdx.z;
    const float* __restrict__ Wh = dir ? Whb : Whf;
    const int b0  = blockIdx.y * 64;
    const int hg0 = blockIdx.x * 32;

    __shared__ float hs[HH][65];      // h tile transposed: hs[k][row], 39 KB
    __shared__ float ws[15][128];     // Wh chunk: ws[k][hl*4+g], 7.5 KB

    const int tid = threadIdx.x;
    // load h tile [64 rows x 150] (coalesced global, conflict-free smem: stride 65)
    for (int i = tid; i < 64 * HH; i += 256) {
        int r = i / HH, k = i - r * HH;
        hs[k][r] = g_h[dir][b0 + r][k];
    }

    const int r0 = (tid >> 4) * 4;       // 4 batch rows
    const int n0 = (tid & 15) * 8;       // 2 hidx * 4 gates
    float acc[4][8];
    #pragma unroll
    for (int r = 0; r < 4; r++)
        #pragma unroll
        for (int c = 0; c < 8; c++) acc[r][c] = 0.f;

    for (int kt = 0; kt < HH; kt += 15) {
        #pragma unroll
        for (int i = 0; i < 8; i++) {            // 15*128 = 1920 elems
            int idx = tid + i * 256;
            if (idx < 15 * 128) {
                int k = idx >> 7, n = idx & 127;
                int hl = n >> 2, g = n & 3;
                int hidx = hg0 + hl;
                ws[k][n] = (hidx < HH) ? Wh[(size_t)(kt + k) * G4 + g * HH + hidx] : 0.f;
            }
        }
        __syncthreads();                          // also guards hs on first iter
        #pragma unroll
        for (int k = 0; k < 15; k++) {
            float a[4], w[8];
            #pragma unroll
            for (int r = 0; r < 4; r++) a[r] = hs[kt + k][r0 + r];
            #pragma unroll
            for (int c = 0; c < 8; c++) w[c] = ws[k][n0 + c];
            #pragma unroll
            for (int r = 0; r < 4; r++)
                #pragma unroll
                for (int c = 0; c < 8; c++)
                    acc[r][c] = fmaf(a[r], w[c], acc[r][c]);
        }
        __syncthreads();
    }

    // fused gate epilogue
    #pragma unroll
    for (int r = 0; r < 4; r++) {
        int b = b0 + r0 + r;
        int len = g_lens[b];
        if (step >= len) continue;               // masked: state & output untouched
        int t = dir ? (len - 1 - step) : step;   // bw reads/writes reversed time
        const float* __restrict__ xz = &g_xz[dir][b * TT + t][0];
        #pragma unroll
        for (int hh = 0; hh < 2; hh++) {
            int hidx = hg0 + (tid & 15) * 2 + hh;
            if (hidx >= HH) continue;
            float zi = acc[r][hh * 4 + 0] + xz[hidx];
            float zj = acc[r][hh * 4 + 1] + xz[HH + hidx];
            float zf = acc[r][hh * 4 + 2] + xz[2 * HH + hidx];
            float zo = acc[r][hh * 4 + 3] + xz[3 * HH + hidx];
            float c  = g_c[dir][b][hidx];
            float cn = c * sigmf(zf + 1.0f) + sigmf(zi) * tanhf(zj);
            float hn = tanhf(cn) * sigmf(zo);
            g_c[dir][b][hidx] = cn;
            g_h[dir][b][hidx] = hn;
            out[(size_t)(b * TT + t) * DIN + dir * HH + hidx] = hn;
        }
    }
}

// ---------------- classifier head (only t = len-1 needed) -------------------
__global__ void classify(const float* __restrict__ finalOut,
                         const float* __restrict__ dW, const float* __restrict__ db,
                         const float* __restrict__ W,  const float* __restrict__ bb,
                         float* __restrict__ out, int out_size)
{
    int b = blockIdx.x;
    __shared__ float xin[DIN];
    __shared__ float hvec[HH];
    __shared__ float lg[2];
    int len = g_lens[b];
    int t = len - 1;                              // lens >= 1 always
    for (int i = threadIdx.x; i < DIN; i += blockDim.x)
        xin[i] = finalOut[(size_t)(b * TT + t) * DIN + i];
    __syncthreads();
    for (int j = threadIdx.x; j < HH; j += blockDim.x) {
        float s = db[j];
        #pragma unroll 4
        for (int k = 0; k < DIN; k++) s = fmaf(xin[k], dW[k * HH + j], s);
        hvec[j] = fmaxf(s, 0.f);
    }
    __syncthreads();
    if (threadIdx.x < 2) {
        float s = bb[threadIdx.x];
        for (int k = 0; k < HH; k++) s = fmaf(hvec[k], W[k * 2 + threadIdx.x], s);
        lg[threadIdx.x] = s;
    }
    __syncthreads();
    if (threadIdx.x == 0) {
        float l0 = lg[0], l1 = lg[1];
        float pred = (l1 > l0) ? 1.f : 0.f;       // argmax, first-max tie -> 0
        if (out_size >= 3 * BB) {
            out[b * 2 + 0] = l0; out[b * 2 + 1] = l1;
            out[2 * BB + b] = pred;
        } else if (out_size >= 2 * BB) {
            out[b * 2 + 0] = l0; out[b * 2 + 1] = l1;
        } else {
            out[b] = pred;
        }
    }
}

// ---------------- launch ----------------------------------------------------
extern "C" void kernel_launch(void* const* d_in, const int* in_sizes, int n_in,
                              void* d_out, int out_size)
{
    const float* X    = (const float*)d_in[0];
    const int*   mask = (const int*)  d_in[1];
    const float* fwk  = (const float*)d_in[2];
    const float* fwb  = (const float*)d_in[3];
    const float* bwk  = (const float*)d_in[4];
    const float* bwb  = (const float*)d_in[5];
    const float* dW   = (const float*)d_in[6];
    const float* db   = (const float*)d_in[7];
    const float* W    = (const float*)d_in[8];
    const float* bb   = (const float*)d_in[9];
    float* out = (float*)d_out;

    float* bufPtr;
    cudaGetSymbolAddress((void**)&bufPtr, g_buf);

    lens_kernel<<<4, 256>>>(mask);

    const float* cur = X;
    for (int l = 0; l < DEPTH; l++) {
        const float* Wfl = fwk + (size_t)l * 450 * G4;
        const float* Wbl = bwk + (size_t)l * 450 * G4;
        xz_gemm<<<dim3(10, 560, 2), 256>>>(cur, Wfl, fwb + l * G4, Wbl, bwb + l * G4);
        zero_states<<<(2 * BB * HH + 255) / 256, 256>>>();
        float* ob = bufPtr + (size_t)(l & 1) * BT * DIN;
        const float* Whf = Wfl + (size_t)DIN * G4;
        const float* Whb = Wbl + (size_t)DIN * G4;
        for (int s = 0; s < TT; s++)
            lstm_step<<<dim3(5, 16, 2), 256>>>(s, Whf, Whb, ob);
        cur = ob;
    }
    classify<<<BB, 256>>>(cur, dW, db, W, bb, out, out_size);
}

// round 2
// speedup vs baseline: 1.0009x; 1.0009x over previous
#include <cuda_runtime.h>
#include <math.h>

#define BB 1024
#define TT 70
#define HH 150
#define DIN 300      // per-layer input width (E = 2H = 300)
#define G4 600       // 4*H
#define BT (BB*TT)   // 71680
#define DEPTH 5

// ---------------- scratch (static device globals; no allocation) ------------
__device__ float g_xz[2][BT][G4];     // precomputed x@Wx+b, per direction (344 MB)
__device__ float g_buf[2][BT][DIN];   // ping-pong layer activations (172 MB)
__device__ float g_h[2][BB][HH];
__device__ float g_c[2][BB][HH];
__device__ int   g_lens[BB];

// ---------------- small kernels ---------------------------------------------
__global__ void lens_kernel(const int* __restrict__ mask) {
    int b = blockIdx.x * blockDim.x + threadIdx.x;
    if (b < BB) {
        int s = 0;
        #pragma unroll
        for (int t = 0; t < TT; t++) s += mask[b * TT + t];
        g_lens[b] = s;
    }
}

__global__ void zero_states() {
    int i = blockIdx.x * blockDim.x + threadIdx.x;
    if (i < 2 * BB * HH) {
        ((float*)g_h)[i] = 0.f;
        ((float*)g_c)[i] = 0.f;
    }
}

// ---------------- input projection: g_xz[dir] = A @ Wx + bias ---------------
// A: [BT, 300] row-major. Wx: rows [0,300) of kernel [450,600]. C: [BT,600].
// Tiles: BM=128, BN=64, BK=20 (300 = 15*20 exact). 256 threads, 8x4 per thread.
__global__ void __launch_bounds__(256) xz_gemm(
    const float* __restrict__ A,
    const float* __restrict__ Wf, const float* __restrict__ bf,
    const float* __restrict__ Wb, const float* __restrict__ bb)
{
    const int dir = blockIdx.z;
    const float* __restrict__ Wg   = dir ? Wb : Wf;
    const float* __restrict__ bias = dir ? bb : bf;
    const int n0 = blockIdx.x * 64;
    const int m0 = blockIdx.y * 128;

    __shared__ float As[20][128];
    __shared__ float Ws[20][64];

    const int tid = threadIdx.x;
    const int tm = (tid >> 4) * 8;   // 0..120 step 8
    const int tn = (tid & 15) * 4;   // 0..60 step 4

    float acc[8][4];
    #pragma unroll
    for (int r = 0; r < 8; r++)
        #pragma unroll
        for (int c = 0; c < 4; c++) acc[r][c] = 0.f;

    for (int kt = 0; kt < DIN; kt += 20) {
        #pragma unroll
        for (int i = 0; i < 10; i++) {                 // 128*20 = 2560 elems
            int idx = tid + i * 256;
            int m = idx / 20, k = idx % 20;
            As[k][m] = A[(size_t)(m0 + m) * DIN + kt + k];
        }
        #pragma unroll
        for (int i = 0; i < 5; i++) {                  // 20*64 = 1280 elems
            int idx = tid + i * 256;
            int k = idx >> 6, n = idx & 63;
            int col = n0 + n;
            Ws[k][n] = (col < G4) ? Wg[(size_t)(kt + k) * G4 + col] : 0.f;
        }
        __syncthreads();
        #pragma unroll
        for (int k = 0; k < 20; k++) {
            float a[8], w[4];
            #pragma unroll
            for (int r = 0; r < 8; r++) a[r] = As[k][tm + r];
            #pragma unroll
            for (int c = 0; c < 4; c++) w[c] = Ws[k][tn + c];
            #pragma unroll
            for (int r = 0; r < 8; r++)
                #pragma unroll
                for (int c = 0; c < 4; c++)
                    acc[r][c] = fmaf(a[r], w[c], acc[r][c]);
        }
        __syncthreads();
    }

    float* __restrict__ Cout = &g_xz[dir][0][0];
    #pragma unroll
    for (int c = 0; c < 4; c++) {
        int col = n0 + tn + c;
        if (col < G4) {
            float bv = bias[col];
            #pragma unroll
            for (int r = 0; r < 8; r++)
                Cout[(size_t)(m0 + tm + r) * G4 + col] = acc[r][c] + bv;
        }
    }
}

// ---------------- fused recurrent step --------------------------------------
// Per step: z = g_xz[dir][b, t] + h @ Wh ; gate math ; update h,c ; write out.
// Block = 64 batch rows x 32 hidx x 4 gates. grid = (5, 16, 2dirs).
__device__ __forceinline__ float sigmf(float x) { return 1.f / (1.f + expf(-x)); }

__global__ void __launch_bounds__(256) lstm_step(
    int step,
    const float* __restrict__ Whf,   // [150,600], rows 300.. of fw kernel
    const float* __restrict__ Whb,
    float* __restrict__ out)         // [BT, 300]
{
    const int dir = blockIdx.z;
    const float* __restrict__ Wh = dir ? Whb : Whf;
    const int b0  = blockIdx.y * 64;
    const int hg0 = blockIdx.x * 32;

    __shared__ float hs[HH][65];      // h tile transposed: hs[k][row], 39 KB
    __shared__ float ws[15][128];     // Wh chunk: ws[k][hl*4+g], 7.5 KB

    const int tid = threadIdx.x;
    // load h tile [64 rows x 150] (coalesced global, conflict-free smem: stride 65)
    for (int i = tid; i < 64 * HH; i += 256) {
        int r = i / HH, k = i - r * HH;
        hs[k][r] = g_h[dir][b0 + r][k];
    }

    const int r0 = (tid >> 4) * 4;       // 4 batch rows
    const int n0 = (tid & 15) * 8;       // 2 hidx * 4 gates
    float acc[4][8];
    #pragma unroll
    for (int r = 0; r < 4; r++)
        #pragma unroll
        for (int c = 0; c < 8; c++) acc[r][c] = 0.f;

    for (int kt = 0; kt < HH; kt += 15) {
        #pragma unroll
        for (int i = 0; i < 8; i++) {            // 15*128 = 1920 elems
            int idx = tid + i * 256;
            if (idx < 15 * 128) {
                int k = idx >> 7, n = idx & 127;
                int hl = n >> 2, g = n & 3;
                int hidx = hg0 + hl;
                ws[k][n] = (hidx < HH) ? Wh[(size_t)(kt + k) * G4 + g * HH + hidx] : 0.f;
            }
        }
        __syncthreads();                          // also guards hs on first iter
        #pragma unroll
        for (int k = 0; k < 15; k++) {
            float a[4], w[8];
            #pragma unroll
            for (int r = 0; r < 4; r++) a[r] = hs[kt + k][r0 + r];
            #pragma unroll
            for (int c = 0; c < 8; c++) w[c] = ws[k][n0 + c];
            #pragma unroll
            for (int r = 0; r < 4; r++)
                #pragma unroll
                for (int c = 0; c < 8; c++)
                    acc[r][c] = fmaf(a[r], w[c], acc[r][c]);
        }
        __syncthreads();
    }

    // fused gate epilogue
    #pragma unroll
    for (int r = 0; r < 4; r++) {
        int b = b0 + r0 + r;
        int len = g_lens[b];
        if (step >= len) continue;               // masked: state & output untouched
        int t = dir ? (len - 1 - step) : step;   // bw reads/writes reversed time
        const float* __restrict__ xz = &g_xz[dir][b * TT + t][0];
        #pragma unroll
        for (int hh = 0; hh < 2; hh++) {
            int hidx = hg0 + (tid & 15) * 2 + hh;
            if (hidx >= HH) continue;
            float zi = acc[r][hh * 4 + 0] + xz[hidx];
            float zj = acc[r][hh * 4 + 1] + xz[HH + hidx];
            float zf = acc[r][hh * 4 + 2] + xz[2 * HH + hidx];
            float zo = acc[r][hh * 4 + 3] + xz[3 * HH + hidx];
            float c  = g_c[dir][b][hidx];
            float cn = c * sigmf(zf + 1.0f) + sigmf(zi) * tanhf(zj);
            float hn = tanhf(cn) * sigmf(zo);
            g_c[dir][b][hidx] = cn;
            g_h[dir][b][hidx] = hn;
            out[(size_t)(b * TT + t) * DIN + dir * HH + hidx] = hn;
        }
    }
}

// ---------------- classifier head (only t = len-1 needed) -------------------
__global__ void classify(const float* __restrict__ finalOut,
                         const float* __restrict__ dW, const float* __restrict__ db,
                         const float* __restrict__ W,  const float* __restrict__ bb,
                         float* __restrict__ out, int out_size)
{
    int b = blockIdx.x;
    __shared__ float xin[DIN];
    __shared__ float hvec[HH];
    __shared__ float lg[2];
    int len = g_lens[b];
    int t = len - 1;                              // lens >= 1 always
    for (int i = threadIdx.x; i < DIN; i += blockDim.x)
        xin[i] = finalOut[(size_t)(b * TT + t) * DIN + i];
    __syncthreads();
    for (int j = threadIdx.x; j < HH; j += blockDim.x) {
        float s = db[j];
        #pragma unroll 4
        for (int k = 0; k < DIN; k++) s = fmaf(xin[k], dW[k * HH + j], s);
        hvec[j] = fmaxf(s, 0.f);
    }
    __syncthreads();
    if (threadIdx.x < 2) {
        float s = bb[threadIdx.x];
        for (int k = 0; k < HH; k++) s = fmaf(hvec[k], W[k * 2 + threadIdx.x], s);
        lg[threadIdx.x] = s;
    }
    __syncthreads();
    if (threadIdx.x == 0) {
        float l0 = lg[0], l1 = lg[1];
        float pred = (l1 > l0) ? 1.f : 0.f;       // argmax, first-max tie -> 0
        if (out_size >= 3 * BB) {
            out[b * 2 + 0] = l0; out[b * 2 + 1] = l1;
            out[2 * BB + b] = pred;
        } else if (out_size >= 2 * BB) {
            out[b * 2 + 0] = l0; out[b * 2 + 1] = l1;
        } else {
            out[b] = pred;
        }
    }
}

// ---------------- launch ----------------------------------------------------
extern "C" void kernel_launch(void* const* d_in, const int* in_sizes, int n_in,
                              void* d_out, int out_size)
{
    const float* X    = (const float*)d_in[0];
    const int*   mask = (const int*)  d_in[1];
    const float* fwk  = (const float*)d_in[2];
    const float* fwb  = (const float*)d_in[3];
    const float* bwk  = (const float*)d_in[4];
    const float* bwb  = (const float*)d_in[5];
    const float* dW   = (const float*)d_in[6];
    const float* db   = (const float*)d_in[7];
    const float* W    = (const float*)d_in[8];
    const float* bb   = (const float*)d_in[9];
    float* out = (float*)d_out;

    float* bufPtr;
    cudaGetSymbolAddress((void**)&bufPtr, g_buf);

    lens_kernel<<<4, 256>>>(mask);

    const float* cur = X;
    for (int l = 0; l < DEPTH; l++) {
        const float* Wfl = fwk + (size_t)l * 450 * G4;
        const float* Wbl = bwk + (size_t)l * 450 * G4;
        xz_gemm<<<dim3(10, 560, 2), 256>>>(cur, Wfl, fwb + l * G4, Wbl, bwb + l * G4);
        zero_states<<<(2 * BB * HH + 255) / 256, 256>>>();
        float* ob = bufPtr + (size_t)(l & 1) * BT * DIN;
        const float* Whf = Wfl + (size_t)DIN * G4;
        const float* Whb = Wbl + (size_t)DIN * G4;
        for (int s = 0; s < TT; s++)
            lstm_step<<<dim3(5, 16, 2), 256>>>(s, Whf, Whb, ob);
        cur = ob;
    }
    classify<<<BB, 256>>>(cur, dW, db, W, bb, out, out_size);
}

// round 3
// speedup vs baseline: 2.3229x; 2.3207x over previous
#include <cuda_runtime.h>
#include <math.h>
#include <stdint.h>

#define BB 1024
#define TT 70
#define HH 150
#define DIN 300
#define G4 600
#define BT (BB*TT)
#define DEPTH 5

typedef unsigned long long ull;

// ---------------- scratch ----------------------------------------------------
__device__ float g_xz[2][BT][G4];     // x@Wx+b per direction
__device__ float g_buf[2][BT][DIN];   // ping-pong layer activations
__device__ float g_h[2][BB][HH];      // h exchange buffer
__device__ int   g_lens[BB];
__device__ int   g_cnt[32*32];        // 32 group counters, 128B apart

// ---------------- f32x2 helpers ----------------------------------------------
__device__ __forceinline__ ull dup2(float x) {
    ull r; asm("mov.b64 %0, {%1, %1};" : "=l"(r) : "f"(x)); return r;
}
__device__ __forceinline__ void fma2(ull &d, ull a, ull b) {
    asm("fma.rn.f32x2 %0, %1, %2, %0;" : "+l"(d) : "l"(a), "l"(b));
}
__device__ __forceinline__ float2 unpk(ull v) {
    float2 r; asm("mov.b64 {%0, %1}, %2;" : "=f"(r.x), "=f"(r.y) : "l"(v)); return r;
}
__device__ __forceinline__ float sigmf(float x) {
    return __fdividef(1.f, 1.f + __expf(-x));
}
__device__ __forceinline__ float tanhff(float x) {
    // tanh(x) = 1 - 2/(exp(2x)+1)
    return 1.f - __fdividef(2.f, __expf(2.f * x) + 1.f);
}

// ---------------- lens + counter reset ---------------------------------------
__global__ void lens_kernel(const int* __restrict__ mask) {
    int b = blockIdx.x * blockDim.x + threadIdx.x;
    if (b < BB) {
        int s = 0;
        #pragma unroll
        for (int t = 0; t < TT; t++) s += mask[b * TT + t];
        g_lens[b] = s;
        g_cnt[b] = 0;   // 1024 threads cover all 32*32 counters
    }
}

// ---------------- input projection GEMM --------------------------------------
// C[BT,600] = A[BT,300] @ W[300,600] + bias, per direction (blockIdx.z).
// BM=128, BN=128, BK=60. 512 threads: warp = 8-row group (broadcast A reads),
// lane = 4-col group. f32x2 accumulation: acc[rowpair][col].
#define XZ_SMEM (60*130*4 + 60*128*4)

__global__ void __launch_bounds__(512) xz_gemm(
    const float* __restrict__ A,
    const float* __restrict__ Wf, const float* __restrict__ bf,
    const float* __restrict__ Wb, const float* __restrict__ bb2)
{
    extern __shared__ float sm[];
    float (*As)[130] = (float(*)[130])sm;             // [60][130] (transposed, padded)
    float (*Ws)[128] = (float(*)[128])(sm + 60*130);  // [60][128]

    const int dir = blockIdx.z;
    const float* __restrict__ Wg   = dir ? Wb : Wf;
    const float* __restrict__ bias = dir ? bb2 : bf;
    const int n0 = blockIdx.x * 128;
    const int m0 = blockIdx.y * 128;
    const int tid = threadIdx.x;
    const int warp = tid >> 5, lane = tid & 31;
    const int r0 = warp * 8;        // 16 warps x 8 rows = 128
    const int c0 = lane * 4;        // 32 lanes x 4 cols = 128
    const bool colok = (n0 + c0 + 3) < G4;

    ull acc[4][4];                   // [rowpair][col]; .x=even row, .y=odd row
    #pragma unroll
    for (int i = 0; i < 4; i++)
        #pragma unroll
        for (int j = 0; j < 4; j++) acc[i][j] = 0ull;

    for (int kt = 0; kt < DIN; kt += 60) {
        #pragma unroll
        for (int i = 0; i < 15; i++) {               // 128 rows x 60 k transpose
            int idx = tid + i * 512;
            int m = idx / 60, k = idx - m * 60;
            As[k][m] = A[(size_t)(m0 + m) * DIN + kt + k];
        }
        #pragma unroll
        for (int i = 0; i < 15; i++) {               // 60 k x 128 n
            int idx = tid + i * 512;
            int k = idx >> 7, n = idx & 127;
            int col = n0 + n;
            Ws[k][n] = (col < G4) ? Wg[(size_t)(kt + k) * G4 + col] : 0.f;
        }
        __syncthreads();
        #pragma unroll 12
        for (int k = 0; k < 60; k++) {
            ull a0 = *(const ull*)&As[k][r0];        // rows r0,r0+1 (warp broadcast)
            ull a1 = *(const ull*)&As[k][r0+2];
            ull a2 = *(const ull*)&As[k][r0+4];
            ull a3 = *(const ull*)&As[k][r0+6];
            float4 wv = *(const float4*)&Ws[k][c0];
            ull w0 = dup2(wv.x), w1 = dup2(wv.y), w2 = dup2(wv.z), w3 = dup2(wv.w);
            fma2(acc[0][0], a0, w0); fma2(acc[0][1], a0, w1);
            fma2(acc[0][2], a0, w2); fma2(acc[0][3], a0, w3);
            fma2(acc[1][0], a1, w0); fma2(acc[1][1], a1, w1);
            fma2(acc[1][2], a1, w2); fma2(acc[1][3], a1, w3);
            fma2(acc[2][0], a2, w0); fma2(acc[2][1], a2, w1);
            fma2(acc[2][2], a2, w2); fma2(acc[2][3], a2, w3);
            fma2(acc[3][0], a3, w0); fma2(acc[3][1], a3, w1);
            fma2(acc[3][2], a3, w2); fma2(acc[3][3], a3, w3);
        }
        __syncthreads();
    }

    if (colok) {
        float4 bv = *(const float4*)&bias[n0 + c0];
        float* __restrict__ out = &g_xz[dir][0][0];
        #pragma unroll
        for (int rp = 0; rp < 4; rp++) {
            float2 v0 = unpk(acc[rp][0]);
            float2 v1 = unpk(acc[rp][1]);
            float2 v2 = unpk(acc[rp][2]);
            float2 v3 = unpk(acc[rp][3]);
            float4 re = {v0.x + bv.x, v1.x + bv.y, v2.x + bv.z, v3.x + bv.w};
            float4 ro = {v0.y + bv.x, v1.y + bv.y, v2.y + bv.z, v3.y + bv.w};
            *(float4*)&out[(size_t)(m0 + r0 + 2*rp)     * G4 + n0 + c0] = re;
            *(float4*)&out[(size_t)(m0 + r0 + 2*rp + 1) * G4 + n0 + c0] = ro;
        }
    }
}

// ---------------- persistent per-layer LSTM ----------------------------------
// Grid: 128 blocks = dir(2) x btile(16, 64 rows) x hq(4, 40 hidx each, padded).
// Block: 320 threads; thread tile = 4 rows x (2 hidx x 4 gates).
// Wh slice cached in smem for all 70 steps; c in registers; h via L2 + 4-block
// software barrier per step.
#define LB 64
#define LNC 160
#define LTH 320
#define LSTM_SMEM (HH*LNC*4 + HH*65*4)

__global__ void __launch_bounds__(LTH, 1) lstm_layer(
    int base,
    const float* __restrict__ Whf, const float* __restrict__ Whb,
    float* __restrict__ out)
{
    extern __shared__ float sm[];
    float (*ws)[LNC] = (float(*)[LNC])sm;          // [150][160]: col = hl*4+g
    float (*hs)[65]  = (float(*)[65])(sm + HH*LNC); // [150][65]: hs[k][row]

    const int blk   = blockIdx.x;
    const int dir   = blk >> 6;
    const int btile = (blk >> 2) & 15;
    const int hq    = blk & 3;
    const int b0    = btile * 64;
    const int hidx0 = hq * 40;
    const float* __restrict__ Wh = dir ? Whb : Whf;
    const int tid = threadIdx.x;
    int* cnt = &g_cnt[(dir * 16 + btile) * 32];

    // Wh slice -> smem, once per layer
    for (int i = tid; i < HH * LNC; i += LTH) {
        int k = i / LNC, n = i - k * LNC;
        int hl = n >> 2, g = n & 3, hidx = hidx0 + hl;
        ws[k][n] = (hidx < HH) ? Wh[(size_t)k * G4 + g * HH + hidx] : 0.f;
    }

    const int rg = tid / 20, cg = tid - rg * 20;
    const int r0 = rg * 4;          // 4 rows
    const int n0 = cg * 8;          // 2 hidx x 4 gates
    const int h0 = hidx0 + cg * 2;  // first hidx

    int len[4];
    #pragma unroll
    for (int r = 0; r < 4; r++) len[r] = g_lens[b0 + r0 + r];

    float cst[4][2] = {{0.f,0.f},{0.f,0.f},{0.f,0.f},{0.f,0.f}};

    for (int step = 0; step < TT; step++) {
        // stage h (step-1 result of all 4 group blocks) into smem
        if (step == 0) {
            for (int i = tid; i < HH * 65; i += LTH) ((float*)hs)[i] = 0.f;
        } else {
            for (int i = tid; i < LB * HH; i += LTH) {
                int r = i / HH, k = i - r * HH;
                hs[k][r] = __ldcg(&g_h[dir][b0 + r][k]);
            }
        }
        __syncthreads();

        ull acc[4][4];               // [row][colpair]
        #pragma unroll
        for (int r = 0; r < 4; r++)
            #pragma unroll
            for (int c = 0; c < 4; c++) acc[r][c] = 0ull;

        #pragma unroll 10
        for (int k = 0; k < HH; k++) {
            float a0f = hs[k][r0], a1f = hs[k][r0+1], a2f = hs[k][r0+2], a3f = hs[k][r0+3];
            ull a0 = dup2(a0f), a1 = dup2(a1f), a2 = dup2(a2f), a3 = dup2(a3f);
            ull w0 = *(const ull*)&ws[k][n0];
            ull w1 = *(const ull*)&ws[k][n0+2];
            ull w2 = *(const ull*)&ws[k][n0+4];
            ull w3 = *(const ull*)&ws[k][n0+6];
            fma2(acc[0][0], a0, w0); fma2(acc[0][1], a0, w1);
            fma2(acc[0][2], a0, w2); fma2(acc[0][3], a0, w3);
            fma2(acc[1][0], a1, w0); fma2(acc[1][1], a1, w1);
            fma2(acc[1][2], a1, w2); fma2(acc[1][3], a1, w3);
            fma2(acc[2][0], a2, w0); fma2(acc[2][1], a2, w1);
            fma2(acc[2][2], a2, w2); fma2(acc[2][3], a2, w3);
            fma2(acc[3][0], a3, w0); fma2(acc[3][1], a3, w1);
            fma2(acc[3][2], a3, w2); fma2(acc[3][3], a3, w3);
        }

        // fused gate epilogue (only valid timesteps touch state/output)
        #pragma unroll
        for (int r = 0; r < 4; r++) {
            if (step < len[r]) {
                int b = b0 + r0 + r;
                int t = dir ? (len[r] - 1 - step) : step;
                const float* __restrict__ xz = &g_xz[dir][b * TT + t][0];
                #pragma unroll
                for (int hh = 0; hh < 2; hh++) {
                    int hidx = h0 + hh;
                    if (hidx < HH) {
                        float2 p0 = unpk(acc[r][hh*2 + 0]);  // gates i, j
                        float2 p1 = unpk(acc[r][hh*2 + 1]);  // gates f, o
                        float zi = p0.x + __ldg(&xz[hidx]);
                        float zj = p0.y + __ldg(&xz[HH + hidx]);
                        float zf = p1.x + __ldg(&xz[2*HH + hidx]);
                        float zo = p1.y + __ldg(&xz[3*HH + hidx]);
                        float c  = cst[r][hh];
                        float cn = c * sigmf(zf + 1.0f) + sigmf(zi) * tanhff(zj);
                        float hn = tanhff(cn) * sigmf(zo);
                        cst[r][hh] = cn;
                        g_h[dir][b][hidx] = hn;
                        out[(size_t)(b * TT + t) * DIN + dir * HH + hidx] = hn;
                    }
                }
            }
        }

        // 4-block group barrier (release h stores, then wait for peers)
        __threadfence();
        __syncthreads();
        if (tid == 0) {
            atomicAdd(cnt, 1);
            int target = 4 * (base + step + 1);
            int v;
            do {
                asm volatile("ld.acquire.gpu.global.b32 %0, [%1];"
                             : "=r"(v) : "l"(cnt) : "memory");
            } while (v < target);
        }
        __syncthreads();
    }
}

// ---------------- classifier head --------------------------------------------
__global__ void classify(const float* __restrict__ finalOut,
                         const float* __restrict__ dW, const float* __restrict__ db,
                         const float* __restrict__ W,  const float* __restrict__ bb,
                         float* __restrict__ out, int out_size)
{
    int b = blockIdx.x;
    __shared__ float xin[DIN];
    __shared__ float hvec[HH];
    __shared__ float lg[2];
    int len = g_lens[b];
    int t = len - 1;
    for (int i = threadIdx.x; i < DIN; i += blockDim.x)
        xin[i] = finalOut[(size_t)(b * TT + t) * DIN + i];
    __syncthreads();
    for (int j = threadIdx.x; j < HH; j += blockDim.x) {
        float s = db[j];
        #pragma unroll 4
        for (int k = 0; k < DIN; k++) s = fmaf(xin[k], dW[k * HH + j], s);
        hvec[j] = fmaxf(s, 0.f);
    }
    __syncthreads();
    if (threadIdx.x < 2) {
        float s = bb[threadIdx.x];
        for (int k = 0; k < HH; k++) s = fmaf(hvec[k], W[k * 2 + threadIdx.x], s);
        lg[threadIdx.x] = s;
    }
    __syncthreads();
    if (threadIdx.x == 0) {
        float l0 = lg[0], l1 = lg[1];
        float pred = (l1 > l0) ? 1.f : 0.f;
        if (out_size >= 3 * BB) {
            out[b * 2 + 0] = l0; out[b * 2 + 1] = l1;
            out[2 * BB + b] = pred;
        } else if (out_size >= 2 * BB) {
            out[b * 2 + 0] = l0; out[b * 2 + 1] = l1;
        } else {
            out[b] = pred;
        }
    }
}

// ---------------- launch ------------------------------------------------------
extern "C" void kernel_launch(void* const* d_in, const int* in_sizes, int n_in,
                              void* d_out, int out_size)
{
    const float* X    = (const float*)d_in[0];
    const int*   mask = (const int*)  d_in[1];
    const float* fwk  = (const float*)d_in[2];
    const float* fwb  = (const float*)d_in[3];
    const float* bwk  = (const float*)d_in[4];
    const float* bwb  = (const float*)d_in[5];
    const float* dW   = (const float*)d_in[6];
    const float* db   = (const float*)d_in[7];
    const float* W    = (const float*)d_in[8];
    const float* bb   = (const float*)d_in[9];
    float* out = (float*)d_out;

    static int configured = 0;
    if (!configured) {
        cudaFuncSetAttribute(xz_gemm,    cudaFuncAttributeMaxDynamicSharedMemorySize, XZ_SMEM);
        cudaFuncSetAttribute(lstm_layer, cudaFuncAttributeMaxDynamicSharedMemorySize, LSTM_SMEM);
        configured = 1;
    }

    float* bufPtr;
    cudaGetSymbolAddress((void**)&bufPtr, g_buf);

    lens_kernel<<<4, 256>>>(mask);

    const float* cur = X;
    for (int l = 0; l < DEPTH; l++) {
        const float* Wfl = fwk + (size_t)l * 450 * G4;
        const float* Wbl = bwk + (size_t)l * 450 * G4;
        xz_gemm<<<dim3(5, 560, 2), 512, XZ_SMEM>>>(cur, Wfl, fwb + l * G4,
                                                   Wbl, bwb + l * G4);
        float* ob = bufPtr + (size_t)(l & 1) * BT * DIN;
        const float* Whf = Wfl + (size_t)DIN * G4;
        const float* Whb = Wbl + (size_t)DIN * G4;
        lstm_layer<<<128, LTH, LSTM_SMEM>>>(l * TT, Whf, Whb, ob);
        cur = ob;
    }
    classify<<<BB, 256>>>(cur, dW, db, W, bb, out, out_size);
}

// round 4
// speedup vs baseline: 2.8808x; 1.2402x over previous
#include <cuda_runtime.h>
#include <math.h>
#include <stdint.h>

#define BB 1024
#define TT 70
#define HH 150
#define DIN 300
#define G4 600
#define BT (BB*TT)
#define DEPTH 5

typedef unsigned long long ull;

// ---------------- scratch ----------------------------------------------------
__device__ float g_xz[2][BT][G4];     // x@Wx+b per direction
__device__ float g_buf[2][BT][DIN];   // ping-pong layer activations
__device__ float g_h[2][BB][HH];      // h exchange buffer
__device__ int   g_lens[BB];
__device__ int   g_cnt[32*32];        // group counters
__device__ int   g_cmap[BT];          // compacted valid-row -> b*TT+t
__device__ int   g_M;                 // number of valid rows

// ---------------- f32x2 helpers ----------------------------------------------
__device__ __forceinline__ ull dup2(float x) {
    ull r; asm("mov.b64 %0, {%1, %1};" : "=l"(r) : "f"(x)); return r;
}
__device__ __forceinline__ void fma2(ull &d, ull a, ull b) {
    asm("fma.rn.f32x2 %0, %1, %2, %0;" : "+l"(d) : "l"(a), "l"(b));
}
__device__ __forceinline__ float2 unpk(ull v) {
    float2 r; asm("mov.b64 {%0, %1}, %2;" : "=f"(r.x), "=f"(r.y) : "l"(v)); return r;
}
__device__ __forceinline__ float sigmf(float x) {
    return __fdividef(1.f, 1.f + __expf(-x));
}
__device__ __forceinline__ float tanhff(float x) {
    return 1.f - __fdividef(2.f, __expf(2.f * x) + 1.f);
}
__device__ __forceinline__ void cp16(uint32_t smem_dst, const void* gsrc) {
    asm volatile("cp.async.ca.shared.global [%0], [%1], 16;"
                 :: "r"(smem_dst), "l"(gsrc) : "memory");
}

// ---------------- lens + scan + cmap + counter reset --------------------------
__global__ void build_cmap(const int* __restrict__ mask) {
    __shared__ int sl[1024];
    int b = threadIdx.x;
    int s = 0;
    #pragma unroll
    for (int t = 0; t < TT; t++) s += mask[b * TT + t];
    g_lens[b] = s;
    sl[b] = s;
    g_cnt[b] = 0;
    __syncthreads();
    // inclusive Hillis-Steele scan
    for (int d = 1; d < 1024; d <<= 1) {
        int v = 0;
        if (b >= d) v = sl[b - d];
        __syncthreads();
        if (b >= d) sl[b] += v;
        __syncthreads();
    }
    int excl = sl[b] - s;
    for (int t = 0; t < s; t++) g_cmap[excl + t] = b * TT + t;
    if (b == 1023) g_M = sl[1023];
}

// ---------------- input projection GEMM (compacted rows) ----------------------
// C[M',600] = gather(A)[M',300] @ W[300,600] + bias, scatter to g_xz rows.
// BM=128, BN=128, BK=50. 256 threads, thread tile 16 rows x 4 cols.
// W double-buffered via cp.async; A reg-prefetched one chunk ahead.
#define XZ_NA 25              // A elems per thread per chunk (128*50/256)
#define XZ_SMEM ((50*134 + 2*50*128 + 128) * 4)

__global__ void __launch_bounds__(256, 2) xz_gemm(
    const float* __restrict__ A,
    const float* __restrict__ Wf, const float* __restrict__ bf,
    const float* __restrict__ Wb, const float* __restrict__ bb2)
{
    const int Mv = g_M;
    const int m0 = blockIdx.y * 128;
    if (m0 >= Mv) return;

    extern __shared__ float sm[];
    float* sAs = sm;                   // [50][134]
    float* sWs = sm + 50 * 134;        // [2][50][128]
    int*   cmi = (int*)(sWs + 2 * 50 * 128);  // [128]

    const int dir = blockIdx.z;
    const float* __restrict__ Wg   = dir ? Wb : Wf;
    const float* __restrict__ bias = dir ? bb2 : bf;
    const int n0 = blockIdx.x * 128;
    const int tid = threadIdx.x;
    const int warp = tid >> 5, lane = tid & 31;
    const int r0 = warp * 16;          // 8 warps x 16 rows
    const int c0 = lane * 4;           // 32 lanes x 4 cols
    const uint32_t sWs_sa = (uint32_t)__cvta_generic_to_shared(sWs);

    // cmap slice
    if (tid < 128) {
        int gm = m0 + tid;
        cmi[tid] = (gm < Mv) ? g_cmap[gm] : 0;
    }
    __syncthreads();

    ull acc[8][4];
    #pragma unroll
    for (int i = 0; i < 8; i++)
        #pragma unroll
        for (int j = 0; j < 4; j++) acc[i][j] = 0ull;

    float areg[XZ_NA];

    // ---- prefetch chunk 0 ----
    #pragma unroll
    for (int i = 0; i < XZ_NA; i++) {
        int idx = tid + i * 256;
        int m = idx / 50, k = idx - 50 * m;
        areg[i] = __ldg(&A[(size_t)cmi[m] * DIN + k]);
    }
    {   // W chunk 0 -> buf 0
        #pragma unroll
        for (int i = 0; i < 7; i++) {
            int idx = tid + i * 256;
            if (idx < 1600) {
                int kr = idx >> 5, c4 = idx & 31;
                int col = n0 + c4 * 4;
                uint32_t dst = sWs_sa + (uint32_t)((kr * 128 + c4 * 4) * 4);
                if (col < G4) cp16(dst, &Wg[(size_t)kr * G4 + col]);
                else *(float4*)(sWs + kr * 128 + c4 * 4) = make_float4(0,0,0,0);
            }
        }
        asm volatile("cp.async.commit_group;" ::: "memory");
    }

    int buf = 0;
    for (int c = 0; c < 6; c++) {
        // store A regs to smem (As free: trailing sync of prev iter)
        #pragma unroll
        for (int i = 0; i < XZ_NA; i++) {
            int idx = tid + i * 256;
            int m = idx / 50, k = idx - 50 * m;
            sAs[k * 134 + m] = areg[i];
        }
        // prefetch next A chunk to regs
        if (c < 5) {
            int kt = (c + 1) * 50;
            #pragma unroll
            for (int i = 0; i < XZ_NA; i++) {
                int idx = tid + i * 256;
                int m = idx / 50, k = idx - 50 * m;
                areg[i] = __ldg(&A[(size_t)cmi[m] * DIN + kt + k]);
            }
        }
        asm volatile("cp.async.wait_group 0;" ::: "memory");
        __syncthreads();
        // issue next W chunk into other buffer (overlaps with compute)
        if (c < 5) {
            int kt = (c + 1) * 50;
            int ob = buf ^ 1;
            #pragma unroll
            for (int i = 0; i < 7; i++) {
                int idx = tid + i * 256;
                if (idx < 1600) {
                    int kr = idx >> 5, c4 = idx & 31;
                    int col = n0 + c4 * 4;
                    uint32_t dst = sWs_sa + (uint32_t)((ob * 6400 + kr * 128 + c4 * 4) * 4);
                    if (col < G4) cp16(dst, &Wg[(size_t)(kt + kr) * G4 + col]);
                    else *(float4*)(sWs + ob * 6400 + kr * 128 + c4 * 4) = make_float4(0,0,0,0);
                }
            }
            asm volatile("cp.async.commit_group;" ::: "memory");
        }

        const float* Wc = sWs + buf * 6400;
        #pragma unroll 10
        for (int k = 0; k < 50; k++) {
            ull a[8];
            #pragma unroll
            for (int rp = 0; rp < 8; rp++)
                a[rp] = *(const ull*)&sAs[k * 134 + r0 + 2 * rp];
            float4 wv = *(const float4*)&Wc[k * 128 + c0];
            ull w0 = dup2(wv.x), w1 = dup2(wv.y), w2 = dup2(wv.z), w3 = dup2(wv.w);
            #pragma unroll
            for (int rp = 0; rp < 8; rp++) {
                fma2(acc[rp][0], a[rp], w0);
                fma2(acc[rp][1], a[rp], w1);
                fma2(acc[rp][2], a[rp], w2);
                fma2(acc[rp][3], a[rp], w3);
            }
        }
        __syncthreads();
        buf ^= 1;
    }

    // epilogue: bias + scatter
    int col0 = n0 + c0;
    if (col0 < G4) {
        float4 bv = *(const float4*)&bias[col0];
        float* __restrict__ out = &g_xz[dir][0][0];
        #pragma unroll
        for (int rp = 0; rp < 8; rp++) {
            float2 v0 = unpk(acc[rp][0]);
            float2 v1 = unpk(acc[rp][1]);
            float2 v2 = unpk(acc[rp][2]);
            float2 v3 = unpk(acc[rp][3]);
            int re = r0 + 2 * rp, ro = re + 1;
            if (m0 + re < Mv) {
                float4 v = {v0.x + bv.x, v1.x + bv.y, v2.x + bv.z, v3.x + bv.w};
                *(float4*)&out[(size_t)cmi[re] * G4 + col0] = v;
            }
            if (m0 + ro < Mv) {
                float4 v = {v0.y + bv.x, v1.y + bv.y, v2.y + bv.z, v3.y + bv.w};
                *(float4*)&out[(size_t)cmi[ro] * G4 + col0] = v;
            }
        }
    }
}

// ---------------- persistent per-layer LSTM (unchanged from R3) ---------------
#define LB 64
#define LNC 160
#define LTH 320
#define LSTM_SMEM (HH*LNC*4 + HH*65*4)

__global__ void __launch_bounds__(LTH, 1) lstm_layer(
    int base,
    const float* __restrict__ Whf, const float* __restrict__ Whb,
    float* __restrict__ out)
{
    extern __shared__ float sm[];
    float (*ws)[LNC] = (float(*)[LNC])sm;           // [150][160]
    float (*hs)[65]  = (float(*)[65])(sm + HH*LNC); // [150][65]

    const int blk   = blockIdx.x;
    const int dir   = blk >> 6;
    const int btile = (blk >> 2) & 15;
    const int hq    = blk & 3;
    const int b0    = btile * 64;
    const int hidx0 = hq * 40;
    const float* __restrict__ Wh = dir ? Whb : Whf;
    const int tid = threadIdx.x;
    int* cnt = &g_cnt[(dir * 16 + btile) * 32];

    for (int i = tid; i < HH * LNC; i += LTH) {
        int k = i / LNC, n = i - k * LNC;
        int hl = n >> 2, g = n & 3, hidx = hidx0 + hl;
        ws[k][n] = (hidx < HH) ? Wh[(size_t)k * G4 + g * HH + hidx] : 0.f;
    }

    const int rg = tid / 20, cg = tid - rg * 20;
    const int r0 = rg * 4;
    const int n0 = cg * 8;
    const int h0 = hidx0 + cg * 2;

    int len[4];
    #pragma unroll
    for (int r = 0; r < 4; r++) len[r] = g_lens[b0 + r0 + r];

    float cst[4][2] = {{0.f,0.f},{0.f,0.f},{0.f,0.f},{0.f,0.f}};

    for (int step = 0; step < TT; step++) {
        if (step == 0) {
            for (int i = tid; i < HH * 65; i += LTH) ((float*)hs)[i] = 0.f;
        } else {
            for (int i = tid; i < LB * HH; i += LTH) {
                int r = i / HH, k = i - r * HH;
                hs[k][r] = __ldcg(&g_h[dir][b0 + r][k]);
            }
        }
        __syncthreads();

        ull acc[4][4];
        #pragma unroll
        for (int r = 0; r < 4; r++)
            #pragma unroll
            for (int c = 0; c < 4; c++) acc[r][c] = 0ull;

        #pragma unroll 10
        for (int k = 0; k < HH; k++) {
            ull a0 = dup2(hs[k][r0]),   a1 = dup2(hs[k][r0+1]);
            ull a2 = dup2(hs[k][r0+2]), a3 = dup2(hs[k][r0+3]);
            ull w0 = *(const ull*)&ws[k][n0];
            ull w1 = *(const ull*)&ws[k][n0+2];
            ull w2 = *(const ull*)&ws[k][n0+4];
            ull w3 = *(const ull*)&ws[k][n0+6];
            fma2(acc[0][0], a0, w0); fma2(acc[0][1], a0, w1);
            fma2(acc[0][2], a0, w2); fma2(acc[0][3], a0, w3);
            fma2(acc[1][0], a1, w0); fma2(acc[1][1], a1, w1);
            fma2(acc[1][2], a1, w2); fma2(acc[1][3], a1, w3);
            fma2(acc[2][0], a2, w0); fma2(acc[2][1], a2, w1);
            fma2(acc[2][2], a2, w2); fma2(acc[2][3], a2, w3);
            fma2(acc[3][0], a3, w0); fma2(acc[3][1], a3, w1);
            fma2(acc[3][2], a3, w2); fma2(acc[3][3], a3, w3);
        }

        #pragma unroll
        for (int r = 0; r < 4; r++) {
            if (step < len[r]) {
                int b = b0 + r0 + r;
                int t = dir ? (len[r] - 1 - step) : step;
                const float* __restrict__ xz = &g_xz[dir][b * TT + t][0];
                #pragma unroll
                for (int hh = 0; hh < 2; hh++) {
                    int hidx = h0 + hh;
                    if (hidx < HH) {
                        float2 p0 = unpk(acc[r][hh*2 + 0]);
                        float2 p1 = unpk(acc[r][hh*2 + 1]);
                        float zi = p0.x + __ldg(&xz[hidx]);
                        float zj = p0.y + __ldg(&xz[HH + hidx]);
                        float zf = p1.x + __ldg(&xz[2*HH + hidx]);
                        float zo = p1.y + __ldg(&xz[3*HH + hidx]);
                        float c  = cst[r][hh];
                        float cn = c * sigmf(zf + 1.0f) + sigmf(zi) * tanhff(zj);
                        float hn = tanhff(cn) * sigmf(zo);
                        cst[r][hh] = cn;
                        g_h[dir][b][hidx] = hn;
                        out[(size_t)(b * TT + t) * DIN + dir * HH + hidx] = hn;
                    }
                }
            }
        }

        __threadfence();
        __syncthreads();
        if (tid == 0) {
            atomicAdd(cnt, 1);
            int target = 4 * (base + step + 1);
            int v;
            do {
                asm volatile("ld.acquire.gpu.global.b32 %0, [%1];"
                             : "=r"(v) : "l"(cnt) : "memory");
            } while (v < target);
        }
        __syncthreads();
    }
}

// ---------------- classifier head --------------------------------------------
__global__ void classify(const float* __restrict__ finalOut,
                         const float* __restrict__ dW, const float* __restrict__ db,
                         const float* __restrict__ W,  const float* __restrict__ bb,
                         float* __restrict__ out, int out_size)
{
    int b = blockIdx.x;
    __shared__ float xin[DIN];
    __shared__ float hvec[HH];
    __shared__ float lg[2];
    int len = g_lens[b];
    int t = len - 1;
    for (int i = threadIdx.x; i < DIN; i += blockDim.x)
        xin[i] = finalOut[(size_t)(b * TT + t) * DIN + i];
    __syncthreads();
    for (int j = threadIdx.x; j < HH; j += blockDim.x) {
        float s = db[j];
        #pragma unroll 4
        for (int k = 0; k < DIN; k++) s = fmaf(xin[k], dW[k * HH + j], s);
        hvec[j] = fmaxf(s, 0.f);
    }
    __syncthreads();
    if (threadIdx.x < 2) {
        float s = bb[threadIdx.x];
        for (int k = 0; k < HH; k++) s = fmaf(hvec[k], W[k * 2 + threadIdx.x], s);
        lg[threadIdx.x] = s;
    }
    __syncthreads();
    if (threadIdx.x == 0) {
        float l0 = lg[0], l1 = lg[1];
        float pred = (l1 > l0) ? 1.f : 0.f;
        if (out_size >= 3 * BB) {
            out[b * 2 + 0] = l0; out[b * 2 + 1] = l1;
            out[2 * BB + b] = pred;
        } else if (out_size >= 2 * BB) {
            out[b * 2 + 0] = l0; out[b * 2 + 1] = l1;
        } else {
            out[b] = pred;
        }
    }
}

// ---------------- launch ------------------------------------------------------
extern "C" void kernel_launch(void* const* d_in, const int* in_sizes, int n_in,
                              void* d_out, int out_size)
{
    const float* X    = (const float*)d_in[0];
    const int*   mask = (const int*)  d_in[1];
    const float* fwk  = (const float*)d_in[2];
    const float* fwb  = (const float*)d_in[3];
    const float* bwk  = (const float*)d_in[4];
    const float* bwb  = (const float*)d_in[5];
    const float* dW   = (const float*)d_in[6];
    const float* db   = (const float*)d_in[7];
    const float* W    = (const float*)d_in[8];
    const float* bb   = (const float*)d_in[9];
    float* out = (float*)d_out;

    static int configured = 0;
    if (!configured) {
        cudaFuncSetAttribute(xz_gemm,    cudaFuncAttributeMaxDynamicSharedMemorySize, XZ_SMEM);
        cudaFuncSetAttribute(lstm_layer, cudaFuncAttributeMaxDynamicSharedMemorySize, LSTM_SMEM);
        configured = 1;
    }

    float* bufPtr;
    cudaGetSymbolAddress((void**)&bufPtr, g_buf);

    build_cmap<<<1, 1024>>>(mask);

    const float* cur = X;
    for (int l = 0; l < DEPTH; l++) {
        const float* Wfl = fwk + (size_t)l * 450 * G4;
        const float* Wbl = bwk + (size_t)l * 450 * G4;
        xz_gemm<<<dim3(5, 560, 2), 256, XZ_SMEM>>>(cur, Wfl, fwb + l * G4,
                                                   Wbl, bwb + l * G4);
        float* ob = bufPtr + (size_t)(l & 1) * BT * DIN;
        const float* Whf = Wfl + (size_t)DIN * G4;
        const float* Whb = Wbl + (size_t)DIN * G4;
        lstm_layer<<<128, LTH, LSTM_SMEM>>>(l * TT, Whf, Whb, ob);
        cur = ob;
    }
    classify<<<BB, 256>>>(cur, dW, db, W, bb, out, out_size);
}

// round 6
// speedup vs baseline: 3.4425x; 1.1950x over previous
#include <cuda_runtime.h>
#include <cuda_bf16.h>
#include <math.h>
#include <stdint.h>

#define BB 1024
#define TT 70
#define HH 150
#define DIN 300
#define G4 600
#define BT (BB*TT)
#define DEPTH 5
#define KP 960            // 3 segments x 320 (300 padded)

typedef unsigned long long ull;

// ---------------- scratch ----------------------------------------------------
__device__ float g_xz[2][BT][G4];
__device__ float g_buf[2][BT][DIN];
__device__ float g_h[2][BB][HH];
__device__ int   g_lens[BB];
__device__ int   g_cnt[32*32];
__device__ int   g_cmap[BT];
__device__ int   g_M;
__device__ unsigned short g_A2[BT][KP];       // split-bf16 A operand (compacted rows)
__device__ unsigned short g_B2[2][640][KP];   // split-bf16 W^T operand per dir

// ---------------- helpers -----------------------------------------------------
__device__ __forceinline__ ull dup2(float x) {
    ull r; asm("mov.b64 %0, {%1, %1};" : "=l"(r) : "f"(x)); return r;
}
__device__ __forceinline__ void fma2(ull &d, ull a, ull b) {
    asm("fma.rn.f32x2 %0, %1, %2, %0;" : "+l"(d) : "l"(a), "l"(b));
}
__device__ __forceinline__ float2 unpk(ull v) {
    float2 r; asm("mov.b64 {%0, %1}, %2;" : "=f"(r.x), "=f"(r.y) : "l"(v)); return r;
}
__device__ __forceinline__ float sigmf(float x) {
    return __fdividef(1.f, 1.f + __expf(-x));
}
__device__ __forceinline__ float tanhff(float x) {
    return 1.f - __fdividef(2.f, __expf(2.f * x) + 1.f);
}
__device__ __forceinline__ void cp16(uint32_t smem_dst, const void* gsrc) {
    asm volatile("cp.async.ca.shared.global [%0], [%1], 16;"
                 :: "r"(smem_dst), "l"(gsrc) : "memory");
}
__device__ __forceinline__ uint32_t smem_u32(const void* p) {
    uint32_t a;
    asm("{ .reg .u64 t; cvta.to.shared.u64 t, %1; cvt.u32.u64 %0, t; }"
        : "=r"(a) : "l"(p));
    return a;
}
#define SWZ(o) ((o) ^ (((o) >> 3) & 0x70))

#define LDSM4(r0,r1,r2,r3,addr) \
    asm volatile("ldmatrix.sync.aligned.m8n8.x4.shared.b16 {%0,%1,%2,%3}, [%4];" \
        : "=r"(r0), "=r"(r1), "=r"(r2), "=r"(r3) : "r"(addr))

#define MMA16816(c,a,b0,b1) \
    asm volatile("mma.sync.aligned.m16n8k16.row.col.f32.bf16.bf16.f32 " \
        "{%0,%1,%2,%3}, {%4,%5,%6,%7}, {%8,%9}, {%0,%1,%2,%3};" \
        : "+f"((c)[0]), "+f"((c)[1]), "+f"((c)[2]), "+f"((c)[3]) \
        : "r"((a)[0]), "r"((a)[1]), "r"((a)[2]), "r"((a)[3]), "r"(b0), "r"(b1))

// ---------------- lens + scan + cmap -----------------------------------------
__global__ void build_cmap(const int* __restrict__ mask) {
    __shared__ int sl[1024];
    int b = threadIdx.x;
    int s = 0;
    #pragma unroll
    for (int t = 0; t < TT; t++) s += mask[b * TT + t];
    g_lens[b] = s;
    sl[b] = s;
    g_cnt[b] = 0;
    __syncthreads();
    for (int d = 1; d < 1024; d <<= 1) {
        int v = 0;
        if (b >= d) v = sl[b - d];
        __syncthreads();
        if (b >= d) sl[b] += v;
        __syncthreads();
    }
    int excl = sl[b] - s;
    for (int t = 0; t < s; t++) g_cmap[excl + t] = b * TT + t;
    if (b == 1023) g_M = sl[1023];
}

// ---------------- operand prep ------------------------------------------------
__device__ __forceinline__ unsigned short bfbits(__nv_bfloat16 h) {
    return *(unsigned short*)&h;
}

// A2[m] = [Ah(320) | Ah(320) | Al(320)] for compacted row m
__global__ void prep_a2(const float* __restrict__ A) {
    int row = blockIdx.x * 8 + (threadIdx.x >> 5);
    int lane = threadIdx.x & 31;
    if (row >= g_M) return;
    const float* a = A + (size_t)g_cmap[row] * DIN;
    unsigned short* o = &g_A2[row][0];
    for (int k = lane; k < 320; k += 32) {
        float v = (k < DIN) ? a[k] : 0.f;
        __nv_bfloat16 hb = __float2bfloat16(v);
        __nv_bfloat16 lb = __float2bfloat16(v - __bfloat162float(hb));
        unsigned short hu = bfbits(hb), lu = bfbits(lb);
        o[k] = hu; o[320 + k] = hu; o[640 + k] = lu;
    }
}

// B2[dir][n] = [Bh | Bl | Bh] with B[n][k] = W[k][n] (transpose)
__global__ void prep_b2(const float* __restrict__ Wf, const float* __restrict__ Wb) {
    int idx = blockIdx.x * blockDim.x + threadIdx.x;
    if (idx >= 2 * 640 * KP) return;
    int dir = idx / (640 * KP);
    int r = idx - dir * 640 * KP;
    int n = r / KP, k = r - n * KP;
    int seg = k / 320, kk = k - seg * 320;
    const float* W = dir ? Wb : Wf;
    float v = (n < G4 && kk < DIN) ? W[(size_t)kk * G4 + n] : 0.f;
    __nv_bfloat16 hb = __float2bfloat16(v);
    unsigned short o;
    if (seg == 1) o = bfbits(__float2bfloat16(v - __bfloat162float(hb)));
    else          o = bfbits(hb);
    g_B2[dir][n][k] = o;
}

// ---------------- tensor-core input projection (mma.sync / ldmatrix) ----------
// D[128,128] = A2tile @ B2tile^T over K'=960 (15 chunks of 64 bf16).
// 8 warps: warp tile 32x64 (wm = wid&3, wn = wid>>2). Double-buffered cp.async.
#define XZ_SMEM_SZ (2*32768 + 1024)

__global__ void __launch_bounds__(256, 2) xz_hmma(
    const float* __restrict__ bf, const float* __restrict__ bb2)
{
    const int Mv = g_M;
    const int m0 = blockIdx.y * 128;
    if (m0 >= Mv) return;
    const int dir = blockIdx.z;
    const int n0 = blockIdx.x * 128;
    const int tid = threadIdx.x;
    const int wid = tid >> 5, lane = tid & 31;

    extern __shared__ char dsm[];
    uint32_t base = (smem_u32(dsm) + 1023) & ~1023u;   // [buf][A 16KB | B 16KB]
    __shared__ int cmi[128];
    if (tid < 128) {
        int gm = m0 + tid;
        cmi[tid] = (gm < Mv) ? g_cmap[gm] : 0;
    }

    const unsigned short* __restrict__ Arow = &g_A2[m0][0];
    const unsigned short* __restrict__ Brow = &g_B2[dir][n0][0];

    // chunk loader: 64 bf16 K-cols (128B/row), swizzled 16B granules, 256 thr
    auto cp_chunk = [&](int c, int b) {
        uint32_t ab = base + (uint32_t)b * 32768u;
        uint32_t bb = ab + 16384u;
        int kof = c * 64;
        #pragma unroll
        for (int i = 0; i < 4; i++) {
            int g2 = tid + i * 256;          // 0..1023
            int row = g2 >> 3, gr = g2 & 7;
            uint32_t off = SWZ((uint32_t)(row * 128 + gr * 16));
            cp16(ab + off, Arow + (size_t)row * KP + kof + gr * 8);
            cp16(bb + off, Brow + (size_t)row * KP + kof + gr * 8);
        }
        asm volatile("cp.async.commit_group;" ::: "memory");
    };

    const int wm0 = (wid & 3) * 32;
    const int wn0 = (wid >> 2) * 64;

    float acc[2][8][4];
    #pragma unroll
    for (int mt = 0; mt < 2; mt++)
        #pragma unroll
        for (int nt = 0; nt < 8; nt++)
            #pragma unroll
            for (int e = 0; e < 4; e++) acc[mt][nt][e] = 0.f;

    cp_chunk(0, 0);

    for (int c = 0; c < 15; c++) {
        if (c + 1 < 15) {
            cp_chunk(c + 1, (c + 1) & 1);
            asm volatile("cp.async.wait_group 1;" ::: "memory");
        } else {
            asm volatile("cp.async.wait_group 0;" ::: "memory");
        }
        __syncthreads();                  // chunk c resident for all warps

        uint32_t ab = base + (uint32_t)(c & 1) * 32768u;
        uint32_t bb = ab + 16384u;
        #pragma unroll
        for (int ks = 0; ks < 4; ks++) {
            uint32_t afr[2][4];
            #pragma unroll
            for (int mt = 0; mt < 2; mt++) {
                int row = wm0 + mt * 16 + (lane & 15);
                int gr  = ks * 2 + (lane >> 4);
                uint32_t addr = ab + SWZ((uint32_t)(row * 128 + gr * 16));
                LDSM4(afr[mt][0], afr[mt][1], afr[mt][2], afr[mt][3], addr);
            }
            uint32_t bfr[8][2];
            #pragma unroll
            for (int nt4 = 0; nt4 < 4; nt4++) {
                int row = wn0 + nt4 * 16 + (lane & 15);
                int gr  = ks * 2 + (lane >> 4);
                uint32_t addr = bb + SWZ((uint32_t)(row * 128 + gr * 16));
                uint32_t r0, r1, r2, r3;
                LDSM4(r0, r1, r2, r3, addr);
                bfr[nt4*2][0]   = r0; bfr[nt4*2][1]   = r2;
                bfr[nt4*2+1][0] = r1; bfr[nt4*2+1][1] = r3;
            }
            #pragma unroll
            for (int mt = 0; mt < 2; mt++)
                #pragma unroll
                for (int nt = 0; nt < 8; nt++)
                    MMA16816(acc[mt][nt], afr[mt], bfr[nt][0], bfr[nt][1]);
        }
        __syncthreads();                  // done reading before overwrite
    }

    // epilogue: bias + scatter via cmap
    const float* __restrict__ bias = dir ? bb2 : bf;
    float* __restrict__ outp = &g_xz[dir][0][0];
    #pragma unroll
    for (int mt = 0; mt < 2; mt++) {
        int r_lo = wm0 + mt * 16 + (lane >> 2);
        int r_hi = r_lo + 8;
        bool v_lo = (m0 + r_lo) < Mv, v_hi = (m0 + r_hi) < Mv;
        #pragma unroll
        for (int nt = 0; nt < 8; nt++) {
            int col = n0 + wn0 + nt * 8 + (lane & 3) * 2;
            if (col + 1 < G4) {
                float bx = __ldg(&bias[col]), by = __ldg(&bias[col + 1]);
                if (v_lo) {
                    float2 v = {acc[mt][nt][0] + bx, acc[mt][nt][1] + by};
                    *(float2*)&outp[(size_t)cmi[r_lo] * G4 + col] = v;
                }
                if (v_hi) {
                    float2 v = {acc[mt][nt][2] + bx, acc[mt][nt][3] + by};
                    *(float2*)&outp[(size_t)cmi[r_hi] * G4 + col] = v;
                }
            }
        }
    }
}

// ---------------- persistent per-layer LSTM (unchanged, proven) ---------------
#define LB 64
#define LNC 160
#define LTH 320
#define LSTM_SMEM (HH*LNC*4 + HH*65*4)

__global__ void __launch_bounds__(LTH, 1) lstm_layer(
    int basestep,
    const float* __restrict__ Whf, const float* __restrict__ Whb,
    float* __restrict__ out)
{
    extern __shared__ float sm[];
    float (*ws)[LNC] = (float(*)[LNC])sm;
    float (*hs)[65]  = (float(*)[65])(sm + HH*LNC);

    const int blk   = blockIdx.x;
    const int dir   = blk >> 6;
    const int btile = (blk >> 2) & 15;
    const int hq    = blk & 3;
    const int b0    = btile * 64;
    const int hidx0 = hq * 40;
    const float* __restrict__ Wh = dir ? Whb : Whf;
    const int tid = threadIdx.x;
    int* cnt = &g_cnt[(dir * 16 + btile) * 32];

    for (int i = tid; i < HH * LNC; i += LTH) {
        int k = i / LNC, n = i - k * LNC;
        int hl = n >> 2, g = n & 3, hidx = hidx0 + hl;
        ws[k][n] = (hidx < HH) ? Wh[(size_t)k * G4 + g * HH + hidx] : 0.f;
    }

    const int rg = tid / 20, cg = tid - rg * 20;
    const int r0 = rg * 4;
    const int n0 = cg * 8;
    const int h0 = hidx0 + cg * 2;

    int len[4];
    #pragma unroll
    for (int r = 0; r < 4; r++) len[r] = g_lens[b0 + r0 + r];

    float cst[4][2] = {{0.f,0.f},{0.f,0.f},{0.f,0.f},{0.f,0.f}};

    for (int step = 0; step < TT; step++) {
        if (step == 0) {
            for (int i = tid; i < HH * 65; i += LTH) ((float*)hs)[i] = 0.f;
        } else {
            for (int i = tid; i < LB * HH; i += LTH) {
                int r = i / HH, k = i - r * HH;
                hs[k][r] = __ldcg(&g_h[dir][b0 + r][k]);
            }
        }
        __syncthreads();

        ull acc[4][4];
        #pragma unroll
        for (int r = 0; r < 4; r++)
            #pragma unroll
            for (int c = 0; c < 4; c++) acc[r][c] = 0ull;

        #pragma unroll 10
        for (int k = 0; k < HH; k++) {
            ull a0 = dup2(hs[k][r0]),   a1 = dup2(hs[k][r0+1]);
            ull a2 = dup2(hs[k][r0+2]), a3 = dup2(hs[k][r0+3]);
            ull w0 = *(const ull*)&ws[k][n0];
            ull w1 = *(const ull*)&ws[k][n0+2];
            ull w2 = *(const ull*)&ws[k][n0+4];
            ull w3 = *(const ull*)&ws[k][n0+6];
            fma2(acc[0][0], a0, w0); fma2(acc[0][1], a0, w1);
            fma2(acc[0][2], a0, w2); fma2(acc[0][3], a0, w3);
            fma2(acc[1][0], a1, w0); fma2(acc[1][1], a1, w1);
            fma2(acc[1][2], a1, w2); fma2(acc[1][3], a1, w3);
            fma2(acc[2][0], a2, w0); fma2(acc[2][1], a2, w1);
            fma2(acc[2][2], a2, w2); fma2(acc[2][3], a2, w3);
            fma2(acc[3][0], a3, w0); fma2(acc[3][1], a3, w1);
            fma2(acc[3][2], a3, w2); fma2(acc[3][3], a3, w3);
        }

        #pragma unroll
        for (int r = 0; r < 4; r++) {
            if (step < len[r]) {
                int b = b0 + r0 + r;
                int t = dir ? (len[r] - 1 - step) : step;
                const float* __restrict__ xz = &g_xz[dir][b * TT + t][0];
                #pragma unroll
                for (int hh = 0; hh < 2; hh++) {
                    int hidx = h0 + hh;
                    if (hidx < HH) {
                        float2 p0 = unpk(acc[r][hh*2 + 0]);
                        float2 p1 = unpk(acc[r][hh*2 + 1]);
                        float zi = p0.x + __ldg(&xz[hidx]);
                        float zj = p0.y + __ldg(&xz[HH + hidx]);
                        float zf = p1.x + __ldg(&xz[2*HH + hidx]);
                        float zo = p1.y + __ldg(&xz[3*HH + hidx]);
                        float c  = cst[r][hh];
                        float cn = c * sigmf(zf + 1.0f) + sigmf(zi) * tanhff(zj);
                        float hn = tanhff(cn) * sigmf(zo);
                        cst[r][hh] = cn;
                        g_h[dir][b][hidx] = hn;
                        out[(size_t)(b * TT + t) * DIN + dir * HH + hidx] = hn;
                    }
                }
            }
        }

        __threadfence();
        __syncthreads();
        if (tid == 0) {
            atomicAdd(cnt, 1);
            int target = 4 * (basestep + step + 1);
            int v;
            do {
                asm volatile("ld.acquire.gpu.global.b32 %0, [%1];"
                             : "=r"(v) : "l"(cnt) : "memory");
            } while (v < target);
        }
        __syncthreads();
    }
}

// ---------------- classifier head --------------------------------------------
__global__ void classify(const float* __restrict__ finalOut,
                         const float* __restrict__ dW, const float* __restrict__ db,
                         const float* __restrict__ W,  const float* __restrict__ bb,
                         float* __restrict__ out, int out_size)
{
    int b = blockIdx.x;
    __shared__ float xin[DIN];
    __shared__ float hvec[HH];
    __shared__ float lg[2];
    int len = g_lens[b];
    int t = len - 1;
    for (int i = threadIdx.x; i < DIN; i += blockDim.x)
        xin[i] = finalOut[(size_t)(b * TT + t) * DIN + i];
    __syncthreads();
    for (int j = threadIdx.x; j < HH; j += blockDim.x) {
        float s = db[j];
        #pragma unroll 4
        for (int k = 0; k < DIN; k++) s = fmaf(xin[k], dW[k * HH + j], s);
        hvec[j] = fmaxf(s, 0.f);
    }
    __syncthreads();
    if (threadIdx.x < 2) {
        float s = bb[threadIdx.x];
        for (int k = 0; k < HH; k++) s = fmaf(hvec[k], W[k * 2 + threadIdx.x], s);
        lg[threadIdx.x] = s;
    }
    __syncthreads();
    if (threadIdx.x == 0) {
        float l0 = lg[0], l1 = lg[1];
        float pred = (l1 > l0) ? 1.f : 0.f;
        if (out_size >= 3 * BB) {
            out[b * 2 + 0] = l0; out[b * 2 + 1] = l1;
            out[2 * BB + b] = pred;
        } else if (out_size >= 2 * BB) {
            out[b * 2 + 0] = l0; out[b * 2 + 1] = l1;
        } else {
            out[b] = pred;
        }
    }
}

// ---------------- launch ------------------------------------------------------
extern "C" void kernel_launch(void* const* d_in, const int* in_sizes, int n_in,
                              void* d_out, int out_size)
{
    const float* X    = (const float*)d_in[0];
    const int*   mask = (const int*)  d_in[1];
    const float* fwk  = (const float*)d_in[2];
    const float* fwb  = (const float*)d_in[3];
    const float* bwk  = (const float*)d_in[4];
    const float* bwb  = (const float*)d_in[5];
    const float* dW   = (const float*)d_in[6];
    const float* db   = (const float*)d_in[7];
    const float* W    = (const float*)d_in[8];
    const float* bb   = (const float*)d_in[9];
    float* out = (float*)d_out;

    static int configured = 0;
    if (!configured) {
        cudaFuncSetAttribute(xz_hmma,    cudaFuncAttributeMaxDynamicSharedMemorySize, XZ_SMEM_SZ);
        cudaFuncSetAttribute(lstm_layer, cudaFuncAttributeMaxDynamicSharedMemorySize, LSTM_SMEM);
        configured = 1;
    }

    float* bufPtr;
    cudaGetSymbolAddress((void**)&bufPtr, g_buf);

    build_cmap<<<1, 1024>>>(mask);

    const float* cur = X;
    for (int l = 0; l < DEPTH; l++) {
        const float* Wfl = fwk + (size_t)l * 450 * G4;
        const float* Wbl = bwk + (size_t)l * 450 * G4;
        prep_b2<<<(2 * 640 * KP + 255) / 256, 256>>>(Wfl, Wbl);
        prep_a2<<<BT / 8, 256>>>(cur);
        xz_hmma<<<dim3(5, 560, 2), 256, XZ_SMEM_SZ>>>(fwb + l * G4, bwb + l * G4);
        float* ob = bufPtr + (size_t)(l & 1) * BT * DIN;
        const float* Whf = Wfl + (size_t)DIN * G4;
        const float* Whb = Wbl + (size_t)DIN * G4;
        lstm_layer<<<128, LTH, LSTM_SMEM>>>(l * TT, Whf, Whb, ob);
        cur = ob;
    }
    classify<<<BB, 256>>>(cur, dW, db, W, bb, out, out_size);
}

// round 8
// speedup vs baseline: 4.2604x; 1.2376x over previous
#include <cuda_runtime.h>
#include <cuda_bf16.h>
#include <math.h>
#include <stdint.h>

#define BB 1024
#define TT 70
#define HH 150
#define DIN 300
#define G4 600
#define BT (BB*TT)
#define DEPTH 5
#define KP 960            // 3 segments x 320 (300 padded)

typedef unsigned long long ull;

// ---------------- scratch ----------------------------------------------------
__device__ float g_xz[2][BT][G4];
__device__ float g_h[2][BB][HH];
__device__ int   g_lens[BB];
__device__ int   g_coff[BB];
__device__ int   g_cnt[32*32];
__device__ int   g_cmap[BT];
__device__ int   g_M;
__device__ unsigned short g_A2[BT][KP];            // split-bf16 activations (compact rows)
__device__ unsigned short g_B2[DEPTH][2][640][KP]; // split-bf16 W^T per layer/dir

// ---------------- helpers -----------------------------------------------------
__device__ __forceinline__ ull dup2(float x) {
    ull r; asm("mov.b64 %0, {%1, %1};" : "=l"(r) : "f"(x)); return r;
}
__device__ __forceinline__ void fma2(ull &d, ull a, ull b) {
    asm("fma.rn.f32x2 %0, %1, %2, %0;" : "+l"(d) : "l"(a), "l"(b));
}
__device__ __forceinline__ float2 unpk(ull v) {
    float2 r; asm("mov.b64 {%0, %1}, %2;" : "=f"(r.x), "=f"(r.y) : "l"(v)); return r;
}
__device__ __forceinline__ float sigmf(float x) {
    return __fdividef(1.f, 1.f + __expf(-x));
}
__device__ __forceinline__ float tanhff(float x) {
    return 1.f - __fdividef(2.f, __expf(2.f * x) + 1.f);
}
__device__ __forceinline__ void cp16(uint32_t smem_dst, const void* gsrc) {
    asm volatile("cp.async.ca.shared.global [%0], [%1], 16;"
                 :: "r"(smem_dst), "l"(gsrc) : "memory");
}
__device__ __forceinline__ uint32_t smem_u32(const void* p) {
    uint32_t a;
    asm("{ .reg .u64 t; cvta.to.shared.u64 t, %1; cvt.u32.u64 %0, t; }"
        : "=r"(a) : "l"(p));
    return a;
}
#define SWZ(o) ((o) ^ (((o) >> 3) & 0x70))

#define LDSM4(r0,r1,r2,r3,addr) \
    asm volatile("ldmatrix.sync.aligned.m8n8.x4.shared.b16 {%0,%1,%2,%3}, [%4];" \
        : "=r"(r0), "=r"(r1), "=r"(r2), "=r"(r3) : "r"(addr))

#define MMA16816(c,a,b0,b1) \
    asm volatile("mma.sync.aligned.m16n8k16.row.col.f32.bf16.bf16.f32 " \
        "{%0,%1,%2,%3}, {%4,%5,%6,%7}, {%8,%9}, {%0,%1,%2,%3};" \
        : "+f"((c)[0]), "+f"((c)[1]), "+f"((c)[2]), "+f"((c)[3]) \
        : "r"((a)[0]), "r"((a)[1]), "r"((a)[2]), "r"((a)[3]), "r"(b0), "r"(b1))

__device__ __forceinline__ unsigned short bfbits(__nv_bfloat16 h) {
    return *(unsigned short*)&h;
}
__device__ __forceinline__ float bf2f(unsigned short u) {
    __nv_bfloat16 h = *(__nv_bfloat16*)&u;
    return __bfloat162float(h);
}

// ---------------- lens + scan + cmap -----------------------------------------
__global__ void build_cmap(const int* __restrict__ mask) {
    __shared__ int sl[1024];
    int b = threadIdx.x;
    int s = 0;
    #pragma unroll
    for (int t = 0; t < TT; t++) s += mask[b * TT + t];
    g_lens[b] = s;
    sl[b] = s;
    g_cnt[b] = 0;
    __syncthreads();
    for (int d = 1; d < 1024; d <<= 1) {
        int v = 0;
        if (b >= d) v = sl[b - d];
        __syncthreads();
        if (b >= d) sl[b] += v;
        __syncthreads();
    }
    int excl = sl[b] - s;
    g_coff[b] = excl;
    for (int t = 0; t < s; t++) g_cmap[excl + t] = b * TT + t;
    if (b == 1023) g_M = sl[1023];
}

// ---------------- operand prep ------------------------------------------------
// A2[m] = [Ah(320) | Ah(320) | Al(320)] from X, layer 0 only (pads stay zeroed)
__global__ void prep_a2(const float* __restrict__ A) {
    int row = blockIdx.x * 8 + (threadIdx.x >> 5);
    int lane = threadIdx.x & 31;
    if (row >= g_M) return;
    const float* a = A + (size_t)g_cmap[row] * DIN;
    unsigned short* o = &g_A2[row][0];
    for (int k = lane; k < 320; k += 32) {
        float v = (k < DIN) ? a[k] : 0.f;
        __nv_bfloat16 hb = __float2bfloat16(v);
        __nv_bfloat16 lb = __float2bfloat16(v - __bfloat162float(hb));
        unsigned short hu = bfbits(hb), lu = bfbits(lb);
        o[k] = hu; o[320 + k] = hu; o[640 + k] = lu;
    }
}

// All layers' B2 in one shot: B2[l][dir][n][k], B[n][k] = W[k][n]
__global__ void prep_b2_all(const float* __restrict__ fwk, const float* __restrict__ bwk) {
    long long idx = (long long)blockIdx.x * blockDim.x + threadIdx.x;
    const long long total = (long long)DEPTH * 2 * 640 * KP;
    if (idx >= total) return;
    int l   = (int)(idx / (2LL * 640 * KP));
    long long r = idx - (long long)l * 2 * 640 * KP;
    int dir = (int)(r / (640LL * KP));
    int r2  = (int)(r - (long long)dir * 640 * KP);
    int n = r2 / KP, k = r2 - n * KP;
    int seg = k / 320, kk = k - seg * 320;
    const float* W = (dir ? bwk : fwk) + (size_t)l * 450 * G4;
    float v = (n < G4 && kk < DIN) ? W[(size_t)kk * G4 + n] : 0.f;
    __nv_bfloat16 hb = __float2bfloat16(v);
    unsigned short o;
    if (seg == 1) o = bfbits(__float2bfloat16(v - __bfloat162float(hb)));
    else          o = bfbits(hb);
    g_B2[l][dir][n][k] = o;
}

// ---------------- tensor-core input projection (mma.sync / ldmatrix) ----------
#define XZ_SMEM_SZ (2*32768 + 1024)

__global__ void __launch_bounds__(256, 2) xz_hmma(
    int layer, const float* __restrict__ bf, const float* __restrict__ bb2)
{
    const int Mv = g_M;
    const int m0 = blockIdx.y * 128;
    if (m0 >= Mv) return;
    const int dir = blockIdx.z;
    const int n0 = blockIdx.x * 128;
    const int tid = threadIdx.x;
    const int wid = tid >> 5, lane = tid & 31;

    extern __shared__ char dsm[];
    uint32_t base = (smem_u32(dsm) + 1023) & ~1023u;
    __shared__ int cmi[128];
    if (tid < 128) {
        int gm = m0 + tid;
        cmi[tid] = (gm < Mv) ? g_cmap[gm] : 0;
    }

    const unsigned short* __restrict__ Arow = &g_A2[m0][0];
    const unsigned short* __restrict__ Brow = &g_B2[layer][dir][n0][0];

    auto cp_chunk = [&](int c, int b) {
        uint32_t ab = base + (uint32_t)b * 32768u;
        uint32_t bb = ab + 16384u;
        int kof = c * 64;
        #pragma unroll
        for (int i = 0; i < 4; i++) {
            int g2 = tid + i * 256;
            int row = g2 >> 3, gr = g2 & 7;
            uint32_t off = SWZ((uint32_t)(row * 128 + gr * 16));
            cp16(ab + off, Arow + (size_t)row * KP + kof + gr * 8);
            cp16(bb + off, Brow + (size_t)row * KP + kof + gr * 8);
        }
        asm volatile("cp.async.commit_group;" ::: "memory");
    };

    const int wm0 = (wid & 3) * 32;
    const int wn0 = (wid >> 2) * 64;

    float acc[2][8][4];
    #pragma unroll
    for (int mt = 0; mt < 2; mt++)
        #pragma unroll
        for (int nt = 0; nt < 8; nt++)
            #pragma unroll
            for (int e = 0; e < 4; e++) acc[mt][nt][e] = 0.f;

    cp_chunk(0, 0);

    for (int c = 0; c < 15; c++) {
        if (c + 1 < 15) {
            cp_chunk(c + 1, (c + 1) & 1);
            asm volatile("cp.async.wait_group 1;" ::: "memory");
        } else {
            asm volatile("cp.async.wait_group 0;" ::: "memory");
        }
        __syncthreads();

        uint32_t ab = base + (uint32_t)(c & 1) * 32768u;
        uint32_t bb = ab + 16384u;
        #pragma unroll
        for (int ks = 0; ks < 4; ks++) {
            uint32_t afr[2][4];
            #pragma unroll
            for (int mt = 0; mt < 2; mt++) {
                int row = wm0 + mt * 16 + (lane & 15);
                int gr  = ks * 2 + (lane >> 4);
                uint32_t addr = ab + SWZ((uint32_t)(row * 128 + gr * 16));
                LDSM4(afr[mt][0], afr[mt][1], afr[mt][2], afr[mt][3], addr);
            }
            uint32_t bfr[8][2];
            #pragma unroll
            for (int nt4 = 0; nt4 < 4; nt4++) {
                int row = wn0 + nt4 * 16 + (lane & 15);
                int gr  = ks * 2 + (lane >> 4);
                uint32_t addr = bb + SWZ((uint32_t)(row * 128 + gr * 16));
                uint32_t r0, r1, r2, r3;
                LDSM4(r0, r1, r2, r3, addr);
                bfr[nt4*2][0]   = r0; bfr[nt4*2][1]   = r2;
                bfr[nt4*2+1][0] = r1; bfr[nt4*2+1][1] = r3;
            }
            #pragma unroll
            for (int mt = 0; mt < 2; mt++)
                #pragma unroll
                for (int nt = 0; nt < 8; nt++)
                    MMA16816(acc[mt][nt], afr[mt], bfr[nt][0], bfr[nt][1]);
        }
        __syncthreads();
    }

    const float* __restrict__ bias = dir ? bb2 : bf;
    float* __restrict__ outp = &g_xz[dir][0][0];
    #pragma unroll
    for (int mt = 0; mt < 2; mt++) {
        int r_lo = wm0 + mt * 16 + (lane >> 2);
        int r_hi = r_lo + 8;
        bool v_lo = (m0 + r_lo) < Mv, v_hi = (m0 + r_hi) < Mv;
        #pragma unroll
        for (int nt = 0; nt < 8; nt++) {
            int col = n0 + wn0 + nt * 8 + (lane & 3) * 2;
            if (col + 1 < G4) {
                float bx = __ldg(&bias[col]), by = __ldg(&bias[col + 1]);
                if (v_lo) {
                    float2 v = {acc[mt][nt][0] + bx, acc[mt][nt][1] + by};
                    *(float2*)&outp[(size_t)cmi[r_lo] * G4 + col] = v;
                }
                if (v_hi) {
                    float2 v = {acc[mt][nt][2] + bx, acc[mt][nt][3] + by};
                    *(float2*)&outp[(size_t)cmi[r_hi] * G4 + col] = v;
                }
            }
        }
    }
}

// ---------------- persistent per-layer LSTM -----------------------------------
// Grid: 128 blocks = dir(2) x btile(8, 128 rows) x hq(8, 20 hidx).
// 640 threads (20 warps, 5/SMSP balanced); thread = 4 rows x 1 hidx x 4 gates.
// Epilogue writes h (fp32, exchange) AND split-bf16 A2 for the next layer.
#define LB 128
#define LNW 80               // 20 hidx * 4 gates
#define LTH 640
#define LSTM_SMEM ((HH*LNW + HH*129) * 4)

__global__ void __launch_bounds__(LTH, 1) lstm_layer(
    int basestep,
    const float* __restrict__ Whf, const float* __restrict__ Whb)
{
    extern __shared__ float sm[];
    float (*ws)[LNW] = (float(*)[LNW])sm;             // [150][80]
    float (*hs)[129] = (float(*)[129])(sm + HH*LNW);  // [150][129]

    const int blk   = blockIdx.x;
    const int dir   = blk >> 6;
    const int btile = (blk >> 3) & 7;
    const int hq    = blk & 7;
    const int b0    = btile * LB;
    const int hidx0 = hq * 20;
    const float* __restrict__ Wh = dir ? Whb : Whf;
    const int tid = threadIdx.x;
    int* cnt = &g_cnt[(dir * 8 + btile) * 32];

    for (int i = tid; i < HH * LNW; i += LTH) {
        int k = i / LNW, n = i - k * LNW;
        int hl = n >> 2, g = n & 3, hidx = hidx0 + hl;
        ws[k][n] = (hidx < HH) ? Wh[(size_t)k * G4 + g * HH + hidx] : 0.f;
    }

    const int rg = tid / 20, cg = tid - rg * 20;   // rg 0..31, cg 0..19
    const int r0 = rg * 4;
    const int n0 = cg * 4;
    const int hidx = hidx0 + cg;
    const bool hok = hidx < HH;
    const int cdir = dir * HH + hidx;

    int len[4], coffr[4];
    #pragma unroll
    for (int r = 0; r < 4; r++) {
        len[r]   = g_lens[b0 + r0 + r];
        coffr[r] = g_coff[b0 + r0 + r];
    }

    float cst[4] = {0.f, 0.f, 0.f, 0.f};

    for (int step = 0; step < TT; step++) {
        // stage h
        if (step == 0) {
            for (int i = tid; i < HH * 129; i += LTH) ((float*)hs)[i] = 0.f;
        } else {
            for (int i = tid; i < LB * HH; i += LTH) {
                int r = i / HH, k = i - r * HH;
                hs[k][r] = __ldcg(&g_h[dir][b0 + r][k]);
            }
        }
        __syncthreads();

        // prefetch xz gate biases (hidden under the FMA loop)
        float xzv[4][4];
        int trow[4];
        #pragma unroll
        for (int r = 0; r < 4; r++) {
            if (step < len[r] && hok) {
                int b = b0 + r0 + r;
                int t = dir ? (len[r] - 1 - step) : step;
                trow[r] = t;
                const float* __restrict__ xz = &g_xz[dir][b * TT + t][0];
                xzv[r][0] = __ldg(&xz[hidx]);
                xzv[r][1] = __ldg(&xz[HH + hidx]);
                xzv[r][2] = __ldg(&xz[2*HH + hidx]);
                xzv[r][3] = __ldg(&xz[3*HH + hidx]);
            }
        }

        ull acc[4][2];
        #pragma unroll
        for (int r = 0; r < 4; r++) { acc[r][0] = 0ull; acc[r][1] = 0ull; }

        #pragma unroll 10
        for (int k = 0; k < HH; k++) {
            ull a0 = dup2(hs[k][r0]),   a1 = dup2(hs[k][r0+1]);
            ull a2 = dup2(hs[k][r0+2]), a3 = dup2(hs[k][r0+3]);
            ull w0 = *(const ull*)&ws[k][n0];
            ull w1 = *(const ull*)&ws[k][n0+2];
            fma2(acc[0][0], a0, w0); fma2(acc[0][1], a0, w1);
            fma2(acc[1][0], a1, w0); fma2(acc[1][1], a1, w1);
            fma2(acc[2][0], a2, w0); fma2(acc[2][1], a2, w1);
            fma2(acc[3][0], a3, w0); fma2(acc[3][1], a3, w1);
        }

        // fused epilogue: gates + state + h exchange + split-bf16 A2 output
        #pragma unroll
        for (int r = 0; r < 4; r++) {
            if (step < len[r] && hok) {
                int b = b0 + r0 + r;
                float2 p0 = unpk(acc[r][0]);   // i, j
                float2 p1 = unpk(acc[r][1]);   // f, o
                float zi = p0.x + xzv[r][0];
                float zj = p0.y + xzv[r][1];
                float zf = p1.x + xzv[r][2];
                float zo = p1.y + xzv[r][3];
                float c  = cst[r];
                float cn = c * sigmf(zf + 1.0f) + sigmf(zi) * tanhff(zj);
                float hn = tanhff(cn) * sigmf(zo);
                cst[r] = cn;
                g_h[dir][b][hidx] = hn;
                int arow = coffr[r] + trow[r];
                __nv_bfloat16 hb = __float2bfloat16(hn);
                unsigned short hu = bfbits(hb);
                unsigned short lu = bfbits(__float2bfloat16(hn - __bfloat162float(hb)));
                unsigned short* ar = &g_A2[arow][0];
                ar[cdir] = hu; ar[320 + cdir] = hu; ar[640 + cdir] = lu;
            }
        }

        // 8-block group barrier
        __threadfence();
        __syncthreads();
        if (tid == 0) {
            atomicAdd(cnt, 1);
            int target = 8 * (basestep + step + 1);
            int v;
            do {
                asm volatile("ld.acquire.gpu.global.b32 %0, [%1];"
                             : "=r"(v) : "l"(cnt) : "memory");
            } while (v < target);
        }
        __syncthreads();
    }
}

// ---------------- classifier head (reads split-bf16 A2) ------------------------
__global__ void classify(const float* __restrict__ dW, const float* __restrict__ db,
                         const float* __restrict__ W,  const float* __restrict__ bb,
                         float* __restrict__ out, int out_size)
{
    int b = blockIdx.x;
    __shared__ float xin[DIN];
    __shared__ float hvec[HH];
    __shared__ float lg[2];
    int len = g_lens[b];
    int row = g_coff[b] + len - 1;
    const unsigned short* ar = &g_A2[row][0];
    for (int i = threadIdx.x; i < DIN; i += blockDim.x)
        xin[i] = bf2f(ar[i]) + bf2f(ar[640 + i]);
    __syncthreads();
    for (int j = threadIdx.x; j < HH; j += blockDim.x) {
        float s = db[j];
        #pragma unroll 4
        for (int k = 0; k < DIN; k++) s = fmaf(xin[k], dW[k * HH + j], s);
        hvec[j] = fmaxf(s, 0.f);
    }
    __syncthreads();
    if (threadIdx.x < 2) {
        float s = bb[threadIdx.x];
        for (int k = 0; k < HH; k++) s = fmaf(hvec[k], W[k * 2 + threadIdx.x], s);
        lg[threadIdx.x] = s;
    }
    __syncthreads();
    if (threadIdx.x == 0) {
        float l0 = lg[0], l1 = lg[1];
        float pred = (l1 > l0) ? 1.f : 0.f;
        if (out_size >= 3 * BB) {
            out[b * 2 + 0] = l0; out[b * 2 + 1] = l1;
            out[2 * BB + b] = pred;
        } else if (out_size >= 2 * BB) {
            out[b * 2 + 0] = l0; out[b * 2 + 1] = l1;
        } else {
            out[b] = pred;
        }
    }
}

// ---------------- launch ------------------------------------------------------
extern "C" void kernel_launch(void* const* d_in, const int* in_sizes, int n_in,
                              void* d_out, int out_size)
{
    const float* X    = (const float*)d_in[0];
    const int*   mask = (const int*)  d_in[1];
    const float* fwk  = (const float*)d_in[2];
    const float* fwb  = (const float*)d_in[3];
    const float* bwk  = (const float*)d_in[4];
    const float* bwb  = (const float*)d_in[5];
    const float* dW   = (const float*)d_in[6];
    const float* db   = (const float*)d_in[7];
    const float* W    = (const float*)d_in[8];
    const float* bb   = (const float*)d_in[9];
    float* out = (float*)d_out;

    static int configured = 0;
    if (!configured) {
        cudaFuncSetAttribute(xz_hmma,    cudaFuncAttributeMaxDynamicSharedMemorySize, XZ_SMEM_SZ);
        cudaFuncSetAttribute(lstm_layer, cudaFuncAttributeMaxDynamicSharedMemorySize, LSTM_SMEM);
        configured = 1;
    }

    build_cmap<<<1, 1024>>>(mask);

    const long long b2_total = (long long)DEPTH * 2 * 640 * KP;
    prep_b2_all<<<(int)((b2_total + 255) / 256), 256>>>(fwk, bwk);
    prep_a2<<<BT / 8, 256>>>(X);

    for (int l = 0; l < DEPTH; l++) {
        xz_hmma<<<dim3(5, 560, 2), 256, XZ_SMEM_SZ>>>(l, fwb + l * G4, bwb + l * G4);
        const float* Whf = fwk + (size_t)l * 450 * G4 + (size_t)DIN * G4;
        const float* Whb = bwk + (size_t)l * 450 * G4 + (size_t)DIN * G4;
        lstm_layer<<<128, LTH, LSTM_SMEM>>>(l * TT, Whf, Whb);
    }
    classify<<<BB, 256>>>(dW, db, W, bb, out, out_size);
}

// round 9
// speedup vs baseline: 5.0349x; 1.1818x over previous
#include <cuda_runtime.h>
#include <cuda_bf16.h>
#include <math.h>
#include <stdint.h>

#define BB 1024
#define TT 70
#define HH 150
#define DIN 300
#define G4 600
#define BT (BB*TT)
#define DEPTH 5
#define KPA 640           // A2: [Ah(320) | Al(320)]
#define KPB 960           // B2: [Bh | Bl | Bh]

typedef unsigned long long ull;

// ---------------- scratch ----------------------------------------------------
__device__ float g_xz[2][BT][G4];
__device__ int   g_lens[BB];
__device__ int   g_coff[BB];
__device__ int   g_cnt[32*32];
__device__ int   g_cmap[BT];
__device__ int   g_M;
__device__ unsigned short g_A2[BT][KPA];            // split-bf16 activations
__device__ unsigned short g_B2[DEPTH][2][640][KPB]; // xz weights (split-bf16, W^T)
__device__ unsigned short g_hA[2][BB][512];         // h in interleaved-3 operand form
__device__ unsigned short g_WhB[DEPTH][2][600][512];// recurrent weights interleaved-3

// ---------------- helpers -----------------------------------------------------
__device__ __forceinline__ float sigmf(float x) {
    return __fdividef(1.f, 1.f + __expf(-x));
}
__device__ __forceinline__ float tanhff(float x) {
    return 1.f - __fdividef(2.f, __expf(2.f * x) + 1.f);
}
__device__ __forceinline__ void cp16(uint32_t smem_dst, const void* gsrc) {
    asm volatile("cp.async.ca.shared.global [%0], [%1], 16;"
                 :: "r"(smem_dst), "l"(gsrc) : "memory");
}
__device__ __forceinline__ uint32_t smem_u32(const void* p) {
    uint32_t a;
    asm("{ .reg .u64 t; cvta.to.shared.u64 t, %1; cvt.u32.u64 %0, t; }"
        : "=r"(a) : "l"(p));
    return a;
}
#define SWZ(o) ((o) ^ (((o) >> 3) & 0x70))

#define LDSM4(r0,r1,r2,r3,addr) \
    asm volatile("ldmatrix.sync.aligned.m8n8.x4.shared.b16 {%0,%1,%2,%3}, [%4];" \
        : "=r"(r0), "=r"(r1), "=r"(r2), "=r"(r3) : "r"(addr))

#define MMA16816(c,a,b0,b1) \
    asm volatile("mma.sync.aligned.m16n8k16.row.col.f32.bf16.bf16.f32 " \
        "{%0,%1,%2,%3}, {%4,%5,%6,%7}, {%8,%9}, {%0,%1,%2,%3};" \
        : "+f"((c)[0]), "+f"((c)[1]), "+f"((c)[2]), "+f"((c)[3]) \
        : "r"((a)[0]), "r"((a)[1]), "r"((a)[2]), "r"((a)[3]), "r"(b0), "r"(b1))

__device__ __forceinline__ unsigned short bfbits(__nv_bfloat16 h) {
    return *(unsigned short*)&h;
}
__device__ __forceinline__ float bf2f(unsigned short u) {
    __nv_bfloat16 h = *(__nv_bfloat16*)&u;
    return __bfloat162float(h);
}

// ---------------- lens + scan + cmap -----------------------------------------
__global__ void build_cmap(const int* __restrict__ mask) {
    __shared__ int sl[1024];
    int b = threadIdx.x;
    int s = 0;
    #pragma unroll
    for (int t = 0; t < TT; t++) s += mask[b * TT + t];
    g_lens[b] = s;
    sl[b] = s;
    g_cnt[b] = 0;
    __syncthreads();
    for (int d = 1; d < 1024; d <<= 1) {
        int v = 0;
        if (b >= d) v = sl[b - d];
        __syncthreads();
        if (b >= d) sl[b] += v;
        __syncthreads();
    }
    int excl = sl[b] - s;
    g_coff[b] = excl;
    for (int t = 0; t < s; t++) g_cmap[excl + t] = b * TT + t;
    if (b == 1023) g_M = sl[1023];
}

// ---------------- operand prep ------------------------------------------------
// A2[m] = [Ah(320) | Al(320)] from X (layer 0 only)
__global__ void prep_a2(const float* __restrict__ A) {
    int row = blockIdx.x * 8 + (threadIdx.x >> 5);
    int lane = threadIdx.x & 31;
    if (row >= g_M) return;
    const float* a = A + (size_t)g_cmap[row] * DIN;
    unsigned short* o = &g_A2[row][0];
    for (int k = lane; k < 320; k += 32) {
        float v = (k < DIN) ? a[k] : 0.f;
        __nv_bfloat16 hb = __float2bfloat16(v);
        __nv_bfloat16 lb = __float2bfloat16(v - __bfloat162float(hb));
        o[k] = bfbits(hb); o[320 + k] = bfbits(lb);
    }
}

// xz weights: B2[l][dir][n][k'] = [Bh|Bl|Bh], B[n][k] = W[k][n]
__global__ void prep_b2_all(const float* __restrict__ fwk, const float* __restrict__ bwk) {
    long long idx = (long long)blockIdx.x * blockDim.x + threadIdx.x;
    const long long total = (long long)DEPTH * 2 * 640 * KPB;
    if (idx >= total) return;
    int l   = (int)(idx / (2LL * 640 * KPB));
    long long r = idx - (long long)l * 2 * 640 * KPB;
    int dir = (int)(r / (640LL * KPB));
    int r2  = (int)(r - (long long)dir * 640 * KPB);
    int n = r2 / KPB, k = r2 - n * KPB;
    int seg = k / 320, kk = k - seg * 320;
    const float* W = (dir ? bwk : fwk) + (size_t)l * 450 * G4;
    float v = (n < G4 && kk < DIN) ? W[(size_t)kk * G4 + n] : 0.f;
    __nv_bfloat16 hb = __float2bfloat16(v);
    unsigned short o;
    if (seg == 1) o = bfbits(__float2bfloat16(v - __bfloat162float(hb)));
    else          o = bfbits(hb);
    g_B2[l][dir][n][k] = o;
}

// recurrent weights: g_WhB[l][dir][n][k'], k'=3k+s: s=1 -> Whl, else Whh
__global__ void prep_whb(const float* __restrict__ fwk, const float* __restrict__ bwk) {
    int idx = blockIdx.x * blockDim.x + threadIdx.x;
    const int total = DEPTH * 2 * 600 * 512;
    if (idx >= total) return;
    int kp = idx & 511;
    int n  = (idx >> 9) % 600;
    int dir = (idx / (512 * 600)) & 1;
    int l   = idx / (512 * 600 * 2);
    unsigned short o = 0;
    if (kp < 450) {
        int k = kp / 3, s = kp - 3 * k;
        const float* W = (dir ? bwk : fwk) + (size_t)l * 450 * G4 + (size_t)(DIN + k) * G4;
        float w = W[n];
        __nv_bfloat16 hb = __float2bfloat16(w);
        if (s == 1) o = bfbits(__float2bfloat16(w - __bfloat162float(hb)));
        else        o = bfbits(hb);
    }
    g_WhB[l][dir][n][kp] = o;
}

// ---------------- tensor-core input projection ---------------------------------
#define XZ_SMEM_SZ (2*32768 + 1024)

__global__ void __launch_bounds__(256, 2) xz_hmma(
    int layer, const float* __restrict__ bf, const float* __restrict__ bb2)
{
    const int Mv = g_M;
    const int m0 = blockIdx.y * 128;
    if (m0 >= Mv) return;
    const int dir = blockIdx.z;
    const int n0 = blockIdx.x * 128;
    const int tid = threadIdx.x;
    const int wid = tid >> 5, lane = tid & 31;

    extern __shared__ char dsm[];
    uint32_t base = (smem_u32(dsm) + 1023) & ~1023u;
    __shared__ int cmi[128];
    if (tid < 128) {
        int gm = m0 + tid;
        cmi[tid] = (gm < Mv) ? g_cmap[gm] : 0;
    }

    const unsigned short* __restrict__ Arow = &g_A2[m0][0];
    const unsigned short* __restrict__ Brow = &g_B2[layer][dir][n0][0];

    auto cp_chunk = [&](int c, int b) {
        uint32_t ab = base + (uint32_t)b * 32768u;
        uint32_t bb = ab + 16384u;
        int akof = (c % 5) * 64 + (c >= 10 ? 320 : 0);   // A2 is [Ah|Al], Ah reused
        int bkof = c * 64;
        #pragma unroll
        for (int i = 0; i < 4; i++) {
            int g2 = tid + i * 256;
            int row = g2 >> 3, gr = g2 & 7;
            uint32_t off = SWZ((uint32_t)(row * 128 + gr * 16));
            cp16(ab + off, Arow + (size_t)row * KPA + akof + gr * 8);
            cp16(bb + off, Brow + (size_t)row * KPB + bkof + gr * 8);
        }
        asm volatile("cp.async.commit_group;" ::: "memory");
    };

    const int wm0 = (wid & 3) * 32;
    const int wn0 = (wid >> 2) * 64;

    float acc[2][8][4];
    #pragma unroll
    for (int mt = 0; mt < 2; mt++)
        #pragma unroll
        for (int nt = 0; nt < 8; nt++)
            #pragma unroll
            for (int e = 0; e < 4; e++) acc[mt][nt][e] = 0.f;

    cp_chunk(0, 0);

    for (int c = 0; c < 15; c++) {
        if (c + 1 < 15) {
            cp_chunk(c + 1, (c + 1) & 1);
            asm volatile("cp.async.wait_group 1;" ::: "memory");
        } else {
            asm volatile("cp.async.wait_group 0;" ::: "memory");
        }
        __syncthreads();

        uint32_t ab = base + (uint32_t)(c & 1) * 32768u;
        uint32_t bb = ab + 16384u;
        #pragma unroll
        for (int ks = 0; ks < 4; ks++) {
            uint32_t afr[2][4];
            #pragma unroll
            for (int mt = 0; mt < 2; mt++) {
                int row = wm0 + mt * 16 + (lane & 15);
                int gr  = ks * 2 + (lane >> 4);
                uint32_t addr = ab + SWZ((uint32_t)(row * 128 + gr * 16));
                LDSM4(afr[mt][0], afr[mt][1], afr[mt][2], afr[mt][3], addr);
            }
            uint32_t bfr[8][2];
            #pragma unroll
            for (int nt4 = 0; nt4 < 4; nt4++) {
                int row = wn0 + nt4 * 16 + (lane & 15);
                int gr  = ks * 2 + (lane >> 4);
                uint32_t addr = bb + SWZ((uint32_t)(row * 128 + gr * 16));
                uint32_t r0, r1, r2, r3;
                LDSM4(r0, r1, r2, r3, addr);
                bfr[nt4*2][0]   = r0; bfr[nt4*2][1]   = r2;
                bfr[nt4*2+1][0] = r1; bfr[nt4*2+1][1] = r3;
            }
            #pragma unroll
            for (int mt = 0; mt < 2; mt++)
                #pragma unroll
                for (int nt = 0; nt < 8; nt++)
                    MMA16816(acc[mt][nt], afr[mt], bfr[nt][0], bfr[nt][1]);
        }
        __syncthreads();
    }

    const float* __restrict__ bias = dir ? bb2 : bf;
    float* __restrict__ outp = &g_xz[dir][0][0];
    #pragma unroll
    for (int mt = 0; mt < 2; mt++) {
        int r_lo = wm0 + mt * 16 + (lane >> 2);
        int r_hi = r_lo + 8;
        bool v_lo = (m0 + r_lo) < Mv, v_hi = (m0 + r_hi) < Mv;
        #pragma unroll
        for (int nt = 0; nt < 8; nt++) {
            int col = n0 + wn0 + nt * 8 + (lane & 3) * 2;
            if (col + 1 < G4) {
                float bx = __ldg(&bias[col]), by = __ldg(&bias[col + 1]);
                if (v_lo) {
                    float2 v = {acc[mt][nt][0] + bx, acc[mt][nt][1] + by};
                    *(float2*)&outp[(size_t)cmi[r_lo] * G4 + col] = v;
                }
                if (v_hi) {
                    float2 v = {acc[mt][nt][2] + bx, acc[mt][nt][3] + by};
                    *(float2*)&outp[(size_t)cmi[r_hi] * G4 + col] = v;
                }
            }
        }
    }
}

// ---------------- persistent per-layer LSTM (mma.sync recurrence) --------------
// Grid: 128 blocks = dir(2) x btile(8, 128 rows) x hq(8, 20 hidx).
// 640 threads / 20 warps (4m x 5n); warp tile 32 rows x 16 gatecols.
// K' = 464 (29 k16) over interleaved-3 split-bf16 h and Wh.
#define LTH2 640
#define SM_A 131072          // 8 chunks x 128 rows x 128B
#define SM_B 81920           // 8 chunks x  80 rows x 128B
#define LSTM2_SMEM (1024 + SM_A + SM_B)
#define KS29 29

__global__ void __launch_bounds__(LTH2, 1) lstm_mma(int layer, int basestep)
{
    extern __shared__ char dsm[];
    uint32_t Ab = (smem_u32(dsm) + 1023) & ~1023u;
    uint32_t Bb = Ab + SM_A;
    char* gA = dsm + (Ab - smem_u32(dsm));
    char* gB = gA + SM_A;

    const int blk   = blockIdx.x;
    const int dir   = blk >> 6;
    const int btile = (blk >> 3) & 7;
    const int hq    = blk & 7;
    const int b0    = btile * 128;
    const int hidx0 = hq * 20;
    const int tid = threadIdx.x;
    const int wid = tid >> 5, lane = tid & 31;
    int* cnt = &g_cnt[(dir * 8 + btile) * 32];

    // zero B smem (covers hidx >= 150 pad rows), then stage weights once
    for (int i = tid; i < SM_B / 16; i += LTH2)
        *(float4*)(gB + i * 16) = make_float4(0, 0, 0, 0);
    __syncthreads();
    for (int i = tid; i < 8 * 80 * 8; i += LTH2) {
        int g = i & 7, r = (i >> 3) % 80, ch = i / 640;
        int hidx = hidx0 + (r >> 2);
        if (hidx < HH) {
            int srow = (r & 3) * HH + hidx;
            cp16(Bb + ch * 10240 + SWZ((uint32_t)(r * 128 + g * 16)),
                 &g_WhB[layer][dir][srow][ch * 64 + g * 8]);
        }
    }
    asm volatile("cp.async.commit_group;" ::: "memory");

    const int wm0 = (wid / 5) * 32;
    const int wn0 = (wid % 5) * 16;

    int rows[2];
    rows[0] = wm0 + (lane >> 2) + ((lane & 1) ? 8 : 0);
    rows[1] = rows[0] + 16;
    int hxs[2];
    hxs[0] = hidx0 + (wid % 5) * 4 + ((lane & 3) >> 1);
    hxs[1] = hxs[0] + 2;

    int len[2], cof[2];
    #pragma unroll
    for (int mt = 0; mt < 2; mt++) {
        len[mt] = g_lens[b0 + rows[mt]];
        cof[mt] = g_coff[b0 + rows[mt]];
    }
    float cst[2][2] = {{0.f, 0.f}, {0.f, 0.f}};

    for (int step = 0; step < TT; step++) {
        // stage A (h in operand form); step 0: h = 0
        if (step == 0) {
            for (int i = tid; i < SM_A / 16; i += LTH2)
                *(float4*)(gA + i * 16) = make_float4(0, 0, 0, 0);
        } else {
            for (int i = tid; i < 8192; i += LTH2) {        // 8ch x 128r x 8g
                int g = i & 7, r = (i >> 3) & 127, ch = i >> 10;
                cp16(Ab + ch * 16384 + SWZ((uint32_t)(r * 128 + g * 16)),
                     &g_hA[dir][b0 + r][ch * 64 + g * 8]);
            }
            asm volatile("cp.async.commit_group;" ::: "memory");
        }
        asm volatile("cp.async.wait_group 0;" ::: "memory");
        __syncthreads();

        // prefetch xz gate biases
        float xzv[2][2][4];
        int trow[2];
        #pragma unroll
        for (int mt = 0; mt < 2; mt++) {
            if (step < len[mt]) {
                trow[mt] = dir ? (len[mt] - 1 - step) : step;
                const float* __restrict__ xz =
                    &g_xz[dir][(b0 + rows[mt]) * TT + trow[mt]][0];
                #pragma unroll
                for (int nt = 0; nt < 2; nt++) {
                    if (hxs[nt] < HH) {
                        #pragma unroll
                        for (int g = 0; g < 4; g++)
                            xzv[mt][nt][g] = __ldg(&xz[g * HH + hxs[nt]]);
                    }
                }
            }
        }

        // GEMM: h @ Wh
        float acc[2][2][4];
        #pragma unroll
        for (int mt = 0; mt < 2; mt++)
            #pragma unroll
            for (int nt = 0; nt < 2; nt++)
                #pragma unroll
                for (int e = 0; e < 4; e++) acc[mt][nt][e] = 0.f;

        #pragma unroll
        for (int ks = 0; ks < KS29; ks++) {
            int ch = ks >> 2, ik = ks & 3;
            uint32_t afr[2][4];
            #pragma unroll
            for (int mt = 0; mt < 2; mt++) {
                int row = wm0 + mt * 16 + (lane & 15);
                uint32_t addr = Ab + ch * 16384 +
                    SWZ((uint32_t)(row * 128 + ik * 32 + (lane >> 4) * 16));
                LDSM4(afr[mt][0], afr[mt][1], afr[mt][2], afr[mt][3], addr);
            }
            int brow = wn0 + (lane & 15);
            uint32_t baddr = Bb + ch * 10240 +
                SWZ((uint32_t)(brow * 128 + ik * 32 + (lane >> 4) * 16));
            uint32_t r0, r1, r2, r3;
            LDSM4(r0, r1, r2, r3, baddr);
            #pragma unroll
            for (int mt = 0; mt < 2; mt++) {
                MMA16816(acc[mt][0], afr[mt], r0, r2);
                MMA16816(acc[mt][1], afr[mt], r1, r3);
            }
        }

        // epilogue: gather gates via shfl, LSTM update, write operands
        #pragma unroll
        for (int mt = 0; mt < 2; mt++) {
            #pragma unroll
            for (int nt = 0; nt < 2; nt++) {
                float c0 = acc[mt][nt][0], c1 = acc[mt][nt][1];
                float c2 = acc[mt][nt][2], c3 = acc[mt][nt][3];
                float ex0 = __shfl_xor_sync(0xffffffffu, c0, 1);
                float ex1 = __shfl_xor_sync(0xffffffffu, c1, 1);
                float ex2 = __shfl_xor_sync(0xffffffffu, c2, 1);
                float ex3 = __shfl_xor_sync(0xffffffffu, c3, 1);
                float zi, zj, zf, zo;
                if ((lane & 1) == 0) { zi = c0;  zj = c1;  zf = ex0; zo = ex1; }
                else                 { zi = ex2; zj = ex3; zf = c2;  zo = c3;  }
                if (step < len[mt] && hxs[nt] < HH) {
                    zi += xzv[mt][nt][0];
                    zj += xzv[mt][nt][1];
                    zf += xzv[mt][nt][2];
                    zo += xzv[mt][nt][3];
                    float c  = cst[mt][nt];
                    float cn = c * sigmf(zf + 1.0f) + sigmf(zi) * tanhff(zj);
                    float hn = tanhff(cn) * sigmf(zo);
                    cst[mt][nt] = cn;
                    int b = b0 + rows[mt], hidx = hxs[nt];
                    __nv_bfloat16 hb = __float2bfloat16(hn);
                    unsigned short hu = bfbits(hb);
                    unsigned short lu =
                        bfbits(__float2bfloat16(hn - __bfloat162float(hb)));
                    unsigned short* hp = &g_hA[dir][b][3 * hidx];
                    hp[0] = hu; hp[1] = hu; hp[2] = lu;
                    int arow = cof[mt] + trow[mt];
                    int cd = dir * HH + hidx;
                    unsigned short* ar = &g_A2[arow][0];
                    ar[cd] = hu; ar[320 + cd] = lu;
                }
            }
        }

        // 8-block group barrier (release folds the fence)
        __syncthreads();
        if (tid == 0) {
            asm volatile("red.release.gpu.global.add.s32 [%0], 1;"
                         :: "l"(cnt) : "memory");
            int target = 8 * (basestep + step + 1);
            int v;
            do {
                asm volatile("ld.acquire.gpu.global.b32 %0, [%1];"
                             : "=r"(v) : "l"(cnt) : "memory");
            } while (v < target);
        }
        __syncthreads();
    }
}

// ---------------- classifier head (reads split-bf16 A2) ------------------------
__global__ void classify(const float* __restrict__ dW, const float* __restrict__ db,
                         const float* __restrict__ W,  const float* __restrict__ bb,
                         float* __restrict__ out, int out_size)
{
    int b = blockIdx.x;
    __shared__ float xin[DIN];
    __shared__ float hvec[HH];
    __shared__ float lg[2];
    int len = g_lens[b];
    int row = g_coff[b] + len - 1;
    const unsigned short* ar = &g_A2[row][0];
    for (int i = threadIdx.x; i < DIN; i += blockDim.x)
        xin[i] = bf2f(ar[i]) + bf2f(ar[320 + i]);
    __syncthreads();
    for (int j = threadIdx.x; j < HH; j += blockDim.x) {
        float s = db[j];
        #pragma unroll 4
        for (int k = 0; k < DIN; k++) s = fmaf(xin[k], dW[k * HH + j], s);
        hvec[j] = fmaxf(s, 0.f);
    }
    __syncthreads();
    if (threadIdx.x < 2) {
        float s = bb[threadIdx.x];
        for (int k = 0; k < HH; k++) s = fmaf(hvec[k], W[k * 2 + threadIdx.x], s);
        lg[threadIdx.x] = s;
    }
    __syncthreads();
    if (threadIdx.x == 0) {
        float l0 = lg[0], l1 = lg[1];
        float pred = (l1 > l0) ? 1.f : 0.f;
        if (out_size >= 3 * BB) {
            out[b * 2 + 0] = l0; out[b * 2 + 1] = l1;
            out[2 * BB + b] = pred;
        } else if (out_size >= 2 * BB) {
            out[b * 2 + 0] = l0; out[b * 2 + 1] = l1;
        } else {
            out[b] = pred;
        }
    }
}

// ---------------- launch ------------------------------------------------------
extern "C" void kernel_launch(void* const* d_in, const int* in_sizes, int n_in,
                              void* d_out, int out_size)
{
    const float* X    = (const float*)d_in[0];
    const int*   mask = (const int*)  d_in[1];
    const float* fwk  = (const float*)d_in[2];
    const float* fwb  = (const float*)d_in[3];
    const float* bwk  = (const float*)d_in[4];
    const float* bwb  = (const float*)d_in[5];
    const float* dW   = (const float*)d_in[6];
    const float* db   = (const float*)d_in[7];
    const float* W    = (const float*)d_in[8];
    const float* bb   = (const float*)d_in[9];
    float* out = (float*)d_out;

    static int configured = 0;
    if (!configured) {
        cudaFuncSetAttribute(xz_hmma,  cudaFuncAttributeMaxDynamicSharedMemorySize, XZ_SMEM_SZ);
        cudaFuncSetAttribute(lstm_mma, cudaFuncAttributeMaxDynamicSharedMemorySize, LSTM2_SMEM);
        configured = 1;
    }

    build_cmap<<<1, 1024>>>(mask);

    const long long b2_total = (long long)DEPTH * 2 * 640 * KPB;
    prep_b2_all<<<(int)((b2_total + 255) / 256), 256>>>(fwk, bwk);
    prep_whb<<<(DEPTH * 2 * 600 * 512 + 255) / 256, 256>>>(fwk, bwk);
    prep_a2<<<BT / 8, 256>>>(X);

    for (int l = 0; l < DEPTH; l++) {
        xz_hmma<<<dim3(5, 560, 2), 256, XZ_SMEM_SZ>>>(l, fwb + l * G4, bwb + l * G4);
        lstm_mma<<<128, LTH2, LSTM2_SMEM>>>(l, l * TT);
    }
    classify<<<BB, 256>>>(dW, db, W, bb, out, out_size);
}